// round 8
// baseline (speedup 1.0000x reference)
#include <cuda_runtime.h>
#include <cuda_bf16.h>
#include <cstdint>

#define UD 10000
#define ID 12000
#define IPAD 12032   // 94*128
#define UPAD 10112   // 79*128

// ---------------- scratch ----------------
__device__ __align__(16) uint16_t g_iT_h[64 * IPAD], g_iT_l[64 * IPAD];  // item_sv^T bf16 hi/lo [k][i]
__device__ __align__(16) uint16_t g_uT_h[64 * UPAD], g_uT_l[64 * UPAD];  // user_sv^T bf16 hi/lo [k][u]
__device__ __align__(16) float    g_lp[3][(size_t)UD * 64];              // K1 partials [u][k]
__device__ __align__(16) float    g_rp[3][(size_t)ID * 64];              // K2 partials [i][k]
__device__ __align__(16) uint16_t g_l_h[UPAD * 64], g_l_l[UPAD * 64];    // left*invL bf16 [u][k]
__device__ __align__(16) uint16_t g_r_h[IPAD * 64], g_r_l[IPAD * 64];    // right^T bf16 [i][k]

// ---------------- helpers ----------------
__device__ __forceinline__ uint32_t smem_u32(const void* p) {
    uint32_t a;
    asm("{ .reg .u64 t; cvta.to.shared.u64 t, %1; cvt.u32.u64 %0, t; }" : "=r"(a) : "l"(p));
    return a;
}
__device__ __forceinline__ void split2(float x0, float x1, uint32_t& h, uint32_t& l) {
    asm("cvt.rn.bf16x2.f32 %0, %1, %2;" : "=r"(h) : "f"(x1), "f"(x0));
    float r0 = x0 - __uint_as_float(h << 16);
    float r1 = x1 - __uint_as_float(h & 0xffff0000u);
    asm("cvt.rn.bf16x2.f32 %0, %1, %2;" : "=r"(l) : "f"(r1), "f"(r0));
}
__device__ __forceinline__ void split1(float x, uint16_t& h, uint16_t& l) {
    uint32_t hh, ll;
    asm("cvt.rn.bf16x2.f32 %0, %1, %2;" : "=r"(hh) : "f"(0.f), "f"(x));
    float r = x - __uint_as_float(hh << 16);
    asm("cvt.rn.bf16x2.f32 %0, %1, %2;" : "=r"(ll) : "f"(0.f), "f"(r));
    h = (uint16_t)hh; l = (uint16_t)ll;
}
__device__ __forceinline__ void ldm4(uint32_t* r, uint32_t a) {
    asm volatile("ldmatrix.sync.aligned.m8n8.x4.shared.b16 {%0,%1,%2,%3},[%4];"
                 : "=r"(r[0]), "=r"(r[1]), "=r"(r[2]), "=r"(r[3]) : "r"(a));
}
__device__ __forceinline__ void ldm4t(uint32_t* r, uint32_t a) {
    asm volatile("ldmatrix.sync.aligned.m8n8.x4.trans.shared.b16 {%0,%1,%2,%3},[%4];"
                 : "=r"(r[0]), "=r"(r[1]), "=r"(r[2]), "=r"(r[3]) : "r"(a));
}
__device__ __forceinline__ void mma_bf16(float* d, const uint32_t* a, uint32_t b0, uint32_t b1) {
    asm volatile("mma.sync.aligned.m16n8k16.row.col.f32.bf16.bf16.f32 "
                 "{%0,%1,%2,%3},{%4,%5,%6,%7},{%8,%9},{%0,%1,%2,%3};"
                 : "+f"(d[0]), "+f"(d[1]), "+f"(d[2]), "+f"(d[3])
                 : "r"(a[0]), "r"(a[1]), "r"(a[2]), "r"(a[3]), "r"(b0), "r"(b1));
}
#define CP16(dst, src) \
    asm volatile("cp.async.cg.shared.global [%0],[%1],16;" :: "r"(dst), "l"(src) : "memory")
#define CPCOMMIT() asm volatile("cp.async.commit_group;" ::: "memory")
#define CPWAIT0()  asm volatile("cp.async.wait_group 0;" ::: "memory")

// ---------------- prep: tiled transpose + bf16 split ----------------
__global__ __launch_bounds__(256) void p_item(const float* __restrict__ isv) {
    __shared__ float st[64][65];
    const int t = threadIdx.x, i0 = blockIdx.x * 64;
#pragma unroll
    for (int q = 0; q < 16; q++) {
        int idx = t + q * 256;
        int il = idx >> 6, k = idx & 63, gi = i0 + il;
        st[il][k] = (gi < ID) ? isv[(size_t)gi * 64 + k] : 0.f;
    }
    __syncthreads();
#pragma unroll
    for (int q = 0; q < 16; q++) {
        int idx = t + q * 256;
        int k = idx >> 6, il = idx & 63;
        uint16_t h, l; split1(st[il][k], h, l);
        g_iT_h[(size_t)k * IPAD + i0 + il] = h;
        g_iT_l[(size_t)k * IPAD + i0 + il] = l;
    }
}
__global__ __launch_bounds__(256) void p_user(const float* __restrict__ usv) {
    __shared__ float st[64][65];
    const int t = threadIdx.x, u0 = blockIdx.x * 64;
#pragma unroll
    for (int q = 0; q < 16; q++) {
        int idx = t + q * 256;
        int ul = idx >> 6, k = idx & 63, gu = u0 + ul;
        st[ul][k] = (gu < UD) ? usv[(size_t)gu * 64 + k] : 0.f;
    }
    __syncthreads();
#pragma unroll
    for (int q = 0; q < 16; q++) {
        int idx = t + q * 256;
        int k = idx >> 6, ul = idx & 63;
        uint16_t h, l; split1(st[ul][k], h, l);
        g_uT_h[(size_t)k * UPAD + u0 + ul] = h;
        g_uT_l[(size_t)k * UPAD + u0 + ul] = l;
    }
}

// ---------------- K1: g_lp[s] = norm_adj @ item_sv  (128-thr CTA, M=64u, N=64k, chunk 32i) -------
// smem 40960: Ah[b]@b*5120, Al[b]@10240+b*5120, Bh[b]@20480+b*5120, Bl[b]@30720+b*5120 (pitch 80)
__global__ __launch_bounds__(128, 4) void k1_mma(const float* __restrict__ A) {
    extern __shared__ __align__(16) char sm[];
    const int t = threadIdx.x, lane = t & 31, w = t >> 5;
    const uint32_t sb = smem_u32(sm);
    const int u0 = blockIdx.x * 64, ibase0 = blockIdx.y * 4000;
    const int m0 = (w & 1) * 32, n0 = (w >> 1) * 32;
    const uint32_t aoff = (uint32_t)(m0 + (lane & 15)) * 80 + ((lane >> 4) << 4);
    const uint32_t boff = (uint32_t)(n0 + (lane & 15)) * 80 + ((lane >> 4) << 4);
    const int brow = t >> 2, bseg = t & 3;

    const int arow = t >> 1, acolf = (t & 1) * 16;
    const bool aok = (u0 + arow) < UD;
    const float* arp = A + (size_t)(u0 + arow) * ID + acolf;

    float acc[2][4][4];
#pragma unroll
    for (int a = 0; a < 2; a++)
#pragma unroll
        for (int b = 0; b < 4; b++)
#pragma unroll
            for (int cc = 0; cc < 4; cc++) acc[a][b][cc] = 0.f;

    float4 av[4];

    auto LDGA = [&](int c) {
        const int ib = ibase0 + c * 32;
#pragma unroll
        for (int j = 0; j < 4; j++)
            av[j] = aok ? *(const float4*)(arp + ib + j * 4)
                        : make_float4(0.f, 0.f, 0.f, 0.f);
    };
    auto CPB = [&](int c, int b) {
        const int ib = ibase0 + c * 32;
#pragma unroll
        for (int q = 0; q < 2; q++) {
            const int row = brow + q * 32;
            const uint32_t d0 = sb + 20480 + b * 5120 + row * 80 + (bseg << 4);
            CP16(d0,         (const void*)(g_iT_h + (size_t)row * IPAD + ib + bseg * 8));
            CP16(d0 + 10240, (const void*)(g_iT_l + (size_t)row * IPAD + ib + bseg * 8));
        }
        CPCOMMIT();
    };
    auto STSA = [&](int b) {
        uint32_t hw[8], lw[8];
#pragma unroll
        for (int j = 0; j < 4; j++) {
            split2(av[j].x, av[j].y, hw[2 * j], lw[2 * j]);
            split2(av[j].z, av[j].w, hw[2 * j + 1], lw[2 * j + 1]);
        }
        char* ab = sm + b * 5120 + arow * 80 + (t & 1) * 32;
        *(uint4*)ab                = make_uint4(hw[0], hw[1], hw[2], hw[3]);
        *(uint4*)(ab + 16)         = make_uint4(hw[4], hw[5], hw[6], hw[7]);
        *(uint4*)(ab + 10240)      = make_uint4(lw[0], lw[1], lw[2], lw[3]);
        *(uint4*)(ab + 10240 + 16) = make_uint4(lw[4], lw[5], lw[6], lw[7]);
    };

    LDGA(0); CPB(0, 0); STSA(0);
    CPWAIT0();
    __syncthreads();

    for (int c = 0; c < 125; c++) {
        const int b = c & 1;
        if (c + 1 < 125) { LDGA(c + 1); CPB(c + 1, b ^ 1); }
        const uint32_t bah = sb + b * 5120,         bal = sb + 10240 + b * 5120;
        const uint32_t bbh = sb + 20480 + b * 5120, bbl = sb + 30720 + b * 5120;
#pragma unroll
        for (int ks = 0; ks < 2; ks++) {
            uint32_t bh[2][4], bl[2][4], ah[2][4], al[2][4];
#pragma unroll
            for (int p = 0; p < 2; p++) {
                ldm4(bh[p], bbh + boff + p * 1280 + ks * 32);
                ldm4(bl[p], bbl + boff + p * 1280 + ks * 32);
            }
#pragma unroll
            for (int mi = 0; mi < 2; mi++) {
                ldm4(ah[mi], bah + aoff + mi * 1280 + ks * 32);
                ldm4(al[mi], bal + aoff + mi * 1280 + ks * 32);
            }
#pragma unroll
            for (int mi = 0; mi < 2; mi++)
#pragma unroll
                for (int nt = 0; nt < 4; nt++) {
                    int p = nt >> 1, j = nt & 1;
                    mma_bf16(acc[mi][nt], ah[mi], bh[p][j], bh[p][j + 2]);
                    mma_bf16(acc[mi][nt], ah[mi], bl[p][j], bl[p][j + 2]);
                    mma_bf16(acc[mi][nt], al[mi], bh[p][j], bh[p][j + 2]);
                }
        }
        if (c + 1 < 125) STSA(b ^ 1);
        CPWAIT0();
        __syncthreads();
    }

    float* dst = g_lp[blockIdx.y];
    const int g = lane >> 2, tg = lane & 3;
#pragma unroll
    for (int mi = 0; mi < 2; mi++)
#pragma unroll
        for (int nt = 0; nt < 4; nt++) {
            int row = u0 + m0 + mi * 16 + g;
            int col = n0 + nt * 8 + tg * 2;
            if (row < UD)     *(float2*)(dst + (size_t)row * 64 + col)       = make_float2(acc[mi][nt][0], acc[mi][nt][1]);
            if (row + 8 < UD) *(float2*)(dst + (size_t)(row + 8) * 64 + col) = make_float2(acc[mi][nt][2], acc[mi][nt][3]);
        }
}

// ---------------- K2: g_rp[s][i][k] = adj^T @ user_sv  (128-thr CTA, M=64i, N=64k, chunk 32u) ----
// smem 38912: Ah[b]@b*4608, Al[b]@9216+b*4608 (pitch 144), Bh[b]@18432+b*5120, Bl[b]@28672+b*5120
__global__ __launch_bounds__(128, 4) void k2_mma(const float* __restrict__ Adj) {
    extern __shared__ __align__(16) char sm[];
    const int t = threadIdx.x, lane = t & 31, w = t >> 5;
    const uint32_t sb = smem_u32(sm);
    const int i0 = blockIdx.x * 64, ubase0 = blockIdx.y * 3360;
    const int m0 = (w & 1) * 32, n0 = (w >> 1) * 32;
    const uint32_t aofft = (uint32_t)((lane & 7) + ((lane >> 4) << 3)) * 144
                         + (uint32_t)(m0 + (((lane >> 3) & 1) << 3)) * 2;
    const uint32_t boff = (uint32_t)(n0 + (lane & 15)) * 80 + ((lane >> 4) << 4);
    const int brow = t >> 2, bseg = t & 3;

    // A loader: thread -> u-row t>>2 (0..31), 16 consecutive i at (t&3)*16
    const int arow = t >> 2, acolf = (t & 3) * 16;
    const bool iok = (i0 + acolf + 16) <= ID;

    float acc[2][4][4];
#pragma unroll
    for (int a = 0; a < 2; a++)
#pragma unroll
        for (int b = 0; b < 4; b++)
#pragma unroll
            for (int cc = 0; cc < 4; cc++) acc[a][b][cc] = 0.f;

    float4 av[4];

    auto LDGA = [&](int c) {
        const int gu = ubase0 + c * 32 + arow;
        const bool ok = iok && (gu < UD);
        const float* p = Adj + (size_t)gu * ID + i0 + acolf;
#pragma unroll
        for (int j = 0; j < 4; j++)
            av[j] = ok ? *(const float4*)(p + j * 4) : make_float4(0.f, 0.f, 0.f, 0.f);
    };
    auto CPB = [&](int c, int b) {
        const int ub = ubase0 + c * 32;
#pragma unroll
        for (int q = 0; q < 2; q++) {
            const int row = brow + q * 32;
            const uint32_t d0 = sb + 18432 + b * 5120 + row * 80 + (bseg << 4);
            CP16(d0,         (const void*)(g_uT_h + (size_t)row * UPAD + ub + bseg * 8));
            CP16(d0 + 10240, (const void*)(g_uT_l + (size_t)row * UPAD + ub + bseg * 8));
        }
        CPCOMMIT();
    };
    auto STSA = [&](int b) {
        uint32_t hw[8], lw[8];
#pragma unroll
        for (int j = 0; j < 4; j++) {
            split2(av[j].x, av[j].y, hw[2 * j], lw[2 * j]);
            split2(av[j].z, av[j].w, hw[2 * j + 1], lw[2 * j + 1]);
        }
        char* ab = sm + b * 4608 + arow * 144 + acolf * 2;
        *(uint4*)ab               = make_uint4(hw[0], hw[1], hw[2], hw[3]);
        *(uint4*)(ab + 16)        = make_uint4(hw[4], hw[5], hw[6], hw[7]);
        *(uint4*)(ab + 9216)      = make_uint4(lw[0], lw[1], lw[2], lw[3]);
        *(uint4*)(ab + 9216 + 16) = make_uint4(lw[4], lw[5], lw[6], lw[7]);
    };

    LDGA(0); CPB(0, 0); STSA(0);
    CPWAIT0();
    __syncthreads();

    for (int c = 0; c < 105; c++) {
        const int b = c & 1;
        if (c + 1 < 105) { LDGA(c + 1); CPB(c + 1, b ^ 1); }
        const uint32_t bah = sb + b * 4608,         bal = sb + 9216 + b * 4608;
        const uint32_t bbh = sb + 18432 + b * 5120, bbl = sb + 28672 + b * 5120;
#pragma unroll
        for (int ks = 0; ks < 2; ks++) {
            uint32_t bh[2][4], bl[2][4], ah[2][4], al[2][4];
#pragma unroll
            for (int p = 0; p < 2; p++) {
                ldm4(bh[p], bbh + boff + p * 1280 + ks * 32);
                ldm4(bl[p], bbl + boff + p * 1280 + ks * 32);
            }
#pragma unroll
            for (int mi = 0; mi < 2; mi++) {
                ldm4t(ah[mi], bah + aofft + mi * 32 + ks * 2304);
                ldm4t(al[mi], bal + aofft + mi * 32 + ks * 2304);
            }
#pragma unroll
            for (int mi = 0; mi < 2; mi++)
#pragma unroll
                for (int nt = 0; nt < 4; nt++) {
                    int p = nt >> 1, j = nt & 1;
                    mma_bf16(acc[mi][nt], ah[mi], bh[p][j], bh[p][j + 2]);
                    mma_bf16(acc[mi][nt], ah[mi], bl[p][j], bl[p][j + 2]);
                    mma_bf16(acc[mi][nt], al[mi], bh[p][j], bh[p][j + 2]);
                }
        }
        if (c + 1 < 105) STSA(b ^ 1);
        CPWAIT0();
        __syncthreads();
    }

    float* dst = g_rp[blockIdx.y];
    const int g = lane >> 2, tg = lane & 3;
#pragma unroll
    for (int mi = 0; mi < 2; mi++)
#pragma unroll
        for (int nt = 0; nt < 4; nt++) {
            int row = i0 + m0 + mi * 16 + g;
            int col = n0 + nt * 8 + tg * 2;
            if (row < ID)     *(float2*)(dst + (size_t)row * 64 + col)       = make_float2(acc[mi][nt][0], acc[mi][nt][1]);
            if (row + 8 < ID) *(float2*)(dst + (size_t)(row + 8) * 64 + col) = make_float2(acc[mi][nt][2], acc[mi][nt][3]);
        }
}

// ---------------- reductions + bf16 split ----------------
__global__ __launch_bounds__(256) void red_l(const float* __restrict__ lam) {
    int idx = blockIdx.x * 256 + threadIdx.x;
    if (idx >= UPAD * 64) return;
    int u = idx >> 6;
    float v = 0.f;
    if (u < UD) v = (g_lp[0][idx] + g_lp[1][idx] + g_lp[2][idx]) / lam[idx & 63];
    split1(v, g_l_h[idx], g_l_l[idx]);
}
__global__ __launch_bounds__(256) void red_r() {
    int idx = blockIdx.x * 256 + threadIdx.x;
    if (idx >= IPAD * 64) return;
    int i = idx >> 6;
    float v = 0.f;
    if (i < ID) v = g_rp[0][idx] + g_rp[1][idx] + g_rp[2][idx];
    split1(v, g_r_h[idx], g_r_l[idx]);
}

// ---------------- K3: out[u][i] = g_l @ g_r^T  (M=128u, N=128i, K=64, smem epilogue) -------------
__global__ __launch_bounds__(256, 2) void k3_mma(float* __restrict__ out) {
    extern __shared__ __align__(16) char sm[];
    const int t = threadIdx.x, lane = t & 31, w = t >> 5;
    const uint32_t sb = smem_u32(sm);
    const int u0 = blockIdx.x * 128, i0 = blockIdx.y * 128;
    const int m0 = (w >> 2) * 64, n0 = (w & 3) * 32;
    const uint32_t abase = (uint32_t)(m0 + (lane & 15)) * 144 + ((lane >> 4) << 4);
    const uint32_t bbase = (uint32_t)(n0 + (lane & 15)) * 144 + ((lane >> 4) << 4);

#pragma unroll
    for (int q = 0; q < 4; q++) {
        int idx = t + q * 256;
        int row = idx >> 3, c8 = (idx & 7) << 3;
        *(uint4*)(sm + row * 144 + c8 * 2)         = *(const uint4*)(g_l_h + (size_t)(u0 + row) * 64 + c8);
        *(uint4*)(sm + 18432 + row * 144 + c8 * 2) = *(const uint4*)(g_l_l + (size_t)(u0 + row) * 64 + c8);
        *(uint4*)(sm + 36864 + row * 144 + c8 * 2) = *(const uint4*)(g_r_h + (size_t)(i0 + row) * 64 + c8);
        *(uint4*)(sm + 55296 + row * 144 + c8 * 2) = *(const uint4*)(g_r_l + (size_t)(i0 + row) * 64 + c8);
    }
    __syncthreads();

    float acc[4][4][4];
#pragma unroll
    for (int a = 0; a < 4; a++)
#pragma unroll
        for (int b = 0; b < 4; b++)
#pragma unroll
            for (int cc = 0; cc < 4; cc++) acc[a][b][cc] = 0.f;

#pragma unroll
    for (int ks = 0; ks < 4; ks++) {
        uint32_t bh[2][4], bl[2][4];
#pragma unroll
        for (int p = 0; p < 2; p++) {
            ldm4(bh[p], sb + 36864 + bbase + p * 2304 + ks * 32);
            ldm4(bl[p], sb + 55296 + bbase + p * 2304 + ks * 32);
        }
#pragma unroll
        for (int mi = 0; mi < 4; mi++) {
            uint32_t ah[4], al[4];
            ldm4(ah, sb + abase + mi * 2304 + ks * 32);
            ldm4(al, sb + 18432 + abase + mi * 2304 + ks * 32);
#pragma unroll
            for (int nt = 0; nt < 4; nt++) {
                int p = nt >> 1, j = nt & 1;
                mma_bf16(acc[mi][nt], ah, bh[p][j], bh[p][j + 2]);
                mma_bf16(acc[mi][nt], ah, bl[p][j], bl[p][j + 2]);
                mma_bf16(acc[mi][nt], al, bh[p][j], bh[p][j + 2]);
            }
        }
    }

    // smem epilogue: stage 128x128 fp32 tile (pitch 544B), then coalesced 128B stores
    __syncthreads();
    const int g = lane >> 2, tg = lane & 3;
#pragma unroll
    for (int mi = 0; mi < 4; mi++)
#pragma unroll
        for (int nt = 0; nt < 4; nt++) {
            int row = m0 + mi * 16 + g;
            int col = n0 + nt * 8 + tg * 2;
            *(float2*)(sm + row * 544 + col * 4)       = make_float2(acc[mi][nt][0], acc[mi][nt][1]);
            *(float2*)(sm + (row + 8) * 544 + col * 4) = make_float2(acc[mi][nt][2], acc[mi][nt][3]);
        }
    __syncthreads();

#pragma unroll
    for (int q = 0; q < 16; q++) {
        int idx = t + q * 256;              // 0..4095
        int row = idx >> 5, c4 = (idx & 31) << 2;
        int gu = u0 + row, gi = i0 + c4;
        if (gu < UD) {
            float4 v = *(const float4*)(sm + row * 544 + c4 * 4);
            if (gi + 4 <= ID) {
                *(float4*)(out + (size_t)gu * ID + gi) = v;
            } else if (gi < ID) {
                float vv[4] = {v.x, v.y, v.z, v.w};
                for (int e = 0; e < ID - gi; e++) out[(size_t)gu * ID + gi + e] = vv[e];
            }
        }
    }
}

// ---------------- launch ----------------
extern "C" void kernel_launch(void* const* d_in, const int* in_sizes, int n_in,
                              void* d_out, int out_size) {
    const float* lambda_mat = (const float*)d_in[0];
    const float* user_sv    = (const float*)d_in[1];
    const float* item_sv    = (const float*)d_in[2];
    const float* adj_mat    = (const float*)d_in[3];
    const float* norm_adj   = (const float*)d_in[4];
    float* out = (float*)d_out;

    cudaFuncSetAttribute(k1_mma, cudaFuncAttributeMaxDynamicSharedMemorySize, 40960);
    cudaFuncSetAttribute(k2_mma, cudaFuncAttributeMaxDynamicSharedMemorySize, 38912);
    cudaFuncSetAttribute(k3_mma, cudaFuncAttributeMaxDynamicSharedMemorySize, 73728);

    p_item<<<IPAD / 64, 256>>>(item_sv);
    p_user<<<UPAD / 64, 256>>>(user_sv);
    k1_mma<<<dim3(157, 3), 128, 40960>>>(norm_adj);
    k2_mma<<<dim3(188, 3), 128, 38912>>>(adj_mat);
    red_l<<<(UPAD * 64) / 256, 256>>>(lambda_mat);
    red_r<<<(IPAD * 64) / 256, 256>>>();
    k3_mma<<<dim3(79, 94), 256, 73728>>>(out);
}

// round 9
// speedup vs baseline: 1.0514x; 1.0514x over previous
#include <cuda_runtime.h>
#include <cuda_bf16.h>
#include <cstdint>

#define UD 10000
#define ID 12000
#define IPAD 12032   // 94*128
#define UPAD 10112   // 79*128

// ---------------- scratch ----------------
__device__ __align__(16) uint16_t g_iT_h[64 * IPAD], g_iT_l[64 * IPAD];  // item_sv^T bf16 hi/lo [k][i]
__device__ __align__(16) uint16_t g_uT_h[64 * UPAD], g_uT_l[64 * UPAD];  // user_sv^T bf16 hi/lo [k][u]
__device__ __align__(16) float    g_lp[3][(size_t)UD * 64];              // K1 partials [u][k]
__device__ __align__(16) float    g_rp[3][(size_t)ID * 64];              // K2 partials [i][k]
__device__ __align__(16) uint16_t g_l_h[UPAD * 64], g_l_l[UPAD * 64];    // left*invL bf16 [u][k]
__device__ __align__(16) uint16_t g_r_h[IPAD * 64], g_r_l[IPAD * 64];    // right^T bf16 [i][k]

// ---------------- helpers ----------------
__device__ __forceinline__ uint32_t smem_u32(const void* p) {
    uint32_t a;
    asm("{ .reg .u64 t; cvta.to.shared.u64 t, %1; cvt.u32.u64 %0, t; }" : "=r"(a) : "l"(p));
    return a;
}
__device__ __forceinline__ void split2(float x0, float x1, uint32_t& h, uint32_t& l) {
    asm("cvt.rn.bf16x2.f32 %0, %1, %2;" : "=r"(h) : "f"(x1), "f"(x0));
    float r0 = x0 - __uint_as_float(h << 16);
    float r1 = x1 - __uint_as_float(h & 0xffff0000u);
    asm("cvt.rn.bf16x2.f32 %0, %1, %2;" : "=r"(l) : "f"(r1), "f"(r0));
}
__device__ __forceinline__ void split1(float x, uint16_t& h, uint16_t& l) {
    uint32_t hh, ll;
    asm("cvt.rn.bf16x2.f32 %0, %1, %2;" : "=r"(hh) : "f"(0.f), "f"(x));
    float r = x - __uint_as_float(hh << 16);
    asm("cvt.rn.bf16x2.f32 %0, %1, %2;" : "=r"(ll) : "f"(0.f), "f"(r));
    h = (uint16_t)hh; l = (uint16_t)ll;
}
__device__ __forceinline__ void ldm4(uint32_t* r, uint32_t a) {
    asm volatile("ldmatrix.sync.aligned.m8n8.x4.shared.b16 {%0,%1,%2,%3},[%4];"
                 : "=r"(r[0]), "=r"(r[1]), "=r"(r[2]), "=r"(r[3]) : "r"(a));
}
__device__ __forceinline__ void ldm4t(uint32_t* r, uint32_t a) {
    asm volatile("ldmatrix.sync.aligned.m8n8.x4.trans.shared.b16 {%0,%1,%2,%3},[%4];"
                 : "=r"(r[0]), "=r"(r[1]), "=r"(r[2]), "=r"(r[3]) : "r"(a));
}
__device__ __forceinline__ void mma_bf16(float* d, const uint32_t* a, uint32_t b0, uint32_t b1) {
    asm volatile("mma.sync.aligned.m16n8k16.row.col.f32.bf16.bf16.f32 "
                 "{%0,%1,%2,%3},{%4,%5,%6,%7},{%8,%9},{%0,%1,%2,%3};"
                 : "+f"(d[0]), "+f"(d[1]), "+f"(d[2]), "+f"(d[3])
                 : "r"(a[0]), "r"(a[1]), "r"(a[2]), "r"(a[3]), "r"(b0), "r"(b1));
}

// ---------------- prep: tiled transpose + bf16 split ----------------
__global__ __launch_bounds__(256) void p_item(const float* __restrict__ isv) {
    __shared__ float st[64][65];
    const int t = threadIdx.x, i0 = blockIdx.x * 64;
#pragma unroll
    for (int q = 0; q < 16; q++) {
        int idx = t + q * 256;
        int il = idx >> 6, k = idx & 63, gi = i0 + il;
        st[il][k] = (gi < ID) ? isv[(size_t)gi * 64 + k] : 0.f;
    }
    __syncthreads();
#pragma unroll
    for (int q = 0; q < 16; q++) {
        int idx = t + q * 256;
        int k = idx >> 6, il = idx & 63;
        uint16_t h, l; split1(st[il][k], h, l);
        g_iT_h[(size_t)k * IPAD + i0 + il] = h;
        g_iT_l[(size_t)k * IPAD + i0 + il] = l;
    }
}
__global__ __launch_bounds__(256) void p_user(const float* __restrict__ usv) {
    __shared__ float st[64][65];
    const int t = threadIdx.x, u0 = blockIdx.x * 64;
#pragma unroll
    for (int q = 0; q < 16; q++) {
        int idx = t + q * 256;
        int ul = idx >> 6, k = idx & 63, gu = u0 + ul;
        st[ul][k] = (gu < UD) ? usv[(size_t)gu * 64 + k] : 0.f;
    }
    __syncthreads();
#pragma unroll
    for (int q = 0; q < 16; q++) {
        int idx = t + q * 256;
        int k = idx >> 6, ul = idx & 63;
        uint16_t h, l; split1(st[ul][k], h, l);
        g_uT_h[(size_t)k * UPAD + u0 + ul] = h;
        g_uT_l[(size_t)k * UPAD + u0 + ul] = l;
    }
}

// ---------------- K1: g_lp[s] = norm_adj @ item_sv  (M=128u, N=64k, Kchunk=32i, 2-buf) ----------
// dyn smem 61440: Ah[b] @ b*10240, Al[b] @ 20480+b*10240, Bh[b] @ 40960+b*5120, Bl[b] @ 51200+b*5120
__global__ __launch_bounds__(256, 2) void k1_mma(const float* __restrict__ A) {
    extern __shared__ __align__(16) char sm[];
    const int t = threadIdx.x, lane = t & 31, w = t >> 5;
    const uint32_t sb = smem_u32(sm);
    const int u0 = blockIdx.x * 128, ibase0 = blockIdx.y * 4000;
    const int m0 = (w >> 1) * 32, n0 = (w & 1) * 32;
    const uint32_t aoff = (uint32_t)(m0 + (lane & 15)) * 80 + ((lane >> 4) << 4);
    const uint32_t boff = (uint32_t)(n0 + (lane & 15)) * 80 + ((lane >> 4) << 4);
    const int brow = t >> 2, bc8 = (t & 3) << 3;

    float acc[2][4][4];
#pragma unroll
    for (int a = 0; a < 2; a++)
#pragma unroll
        for (int b = 0; b < 4; b++)
#pragma unroll
            for (int cc = 0; cc < 4; cc++) acc[a][b][cc] = 0.f;

    float2 ar[8]; uint4 b4h, b4l;

    auto LDGf = [&](int c) {
        const int ib = ibase0 + c * 32;
#pragma unroll
        for (int q = 0; q < 8; q++) {
            int pidx = t + q * 256;
            int aul = pidx >> 4, ic2 = (pidx & 15) << 1;
            int gu = u0 + aul;
            ar[q] = (gu < UD) ? *(const float2*)(A + (size_t)gu * ID + ib + ic2)
                              : make_float2(0.f, 0.f);
        }
        b4h = *(const uint4*)(g_iT_h + (size_t)brow * IPAD + ib + bc8);
        b4l = *(const uint4*)(g_iT_l + (size_t)brow * IPAD + ib + bc8);
    };
    auto STSf = [&](int b) {
        char* ab = sm + b * 10240;
        char* al = sm + 20480 + b * 10240;
#pragma unroll
        for (int q = 0; q < 8; q++) {
            int pidx = t + q * 256;
            int aul = pidx >> 4, ic2 = (pidx & 15) << 1;
            uint32_t h, l; split2(ar[q].x, ar[q].y, h, l);
            *(uint32_t*)(ab + aul * 80 + ic2 * 2) = h;
            *(uint32_t*)(al + aul * 80 + ic2 * 2) = l;
        }
        *(uint4*)(sm + 40960 + b * 5120 + brow * 80 + ((t & 3) << 4)) = b4h;
        *(uint4*)(sm + 51200 + b * 5120 + brow * 80 + ((t & 3) << 4)) = b4l;
    };

    LDGf(0);
    STSf(0);
    __syncthreads();

    for (int c = 0; c < 125; c++) {
        const int b = c & 1;
        if (c + 1 < 125) LDGf(c + 1);
        const uint32_t bah = sb + b * 10240,        bal = sb + 20480 + b * 10240;
        const uint32_t bbh = sb + 40960 + b * 5120, bbl = sb + 51200 + b * 5120;
#pragma unroll
        for (int ks = 0; ks < 2; ks++) {
            uint32_t bh[2][4], bl[2][4], ah[2][4], al[2][4];
#pragma unroll
            for (int p = 0; p < 2; p++) {
                ldm4(bh[p], bbh + boff + p * 1280 + ks * 32);
                ldm4(bl[p], bbl + boff + p * 1280 + ks * 32);
            }
#pragma unroll
            for (int mi = 0; mi < 2; mi++) {
                ldm4(ah[mi], bah + aoff + mi * 1280 + ks * 32);
                ldm4(al[mi], bal + aoff + mi * 1280 + ks * 32);
            }
            // pass-major: 8 independent MMAs per pass -> RAW distance 8
#pragma unroll
            for (int mi = 0; mi < 2; mi++)
#pragma unroll
                for (int nt = 0; nt < 4; nt++) {
                    int p = nt >> 1, j = nt & 1;
                    mma_bf16(acc[mi][nt], ah[mi], bh[p][j], bh[p][j + 2]);
                }
#pragma unroll
            for (int mi = 0; mi < 2; mi++)
#pragma unroll
                for (int nt = 0; nt < 4; nt++) {
                    int p = nt >> 1, j = nt & 1;
                    mma_bf16(acc[mi][nt], ah[mi], bl[p][j], bl[p][j + 2]);
                }
#pragma unroll
            for (int mi = 0; mi < 2; mi++)
#pragma unroll
                for (int nt = 0; nt < 4; nt++) {
                    int p = nt >> 1, j = nt & 1;
                    mma_bf16(acc[mi][nt], al[mi], bh[p][j], bh[p][j + 2]);
                }
        }
        if (c + 1 < 125) STSf(b ^ 1);
        __syncthreads();
    }

    float* dst = g_lp[blockIdx.y];
    const int g = lane >> 2, tg = lane & 3;
#pragma unroll
    for (int mi = 0; mi < 2; mi++)
#pragma unroll
        for (int nt = 0; nt < 4; nt++) {
            int row = u0 + m0 + mi * 16 + g;
            int col = n0 + nt * 8 + tg * 2;
            if (row < UD)     *(float2*)(dst + (size_t)row * 64 + col)       = make_float2(acc[mi][nt][0], acc[mi][nt][1]);
            if (row + 8 < UD) *(float2*)(dst + (size_t)(row + 8) * 64 + col) = make_float2(acc[mi][nt][2], acc[mi][nt][3]);
        }
}

// ---------------- K2: g_rp[s][i][k] = adj^T @ user_sv  (M=128i, N=64k, Kchunk=32u, 2-buf) --------
// dyn smem 55296: Ah[b] @ b*8704, Al[b] @ 17408+b*8704, Bh[b] @ 34816+b*5120, Bl[b] @ 45056+b*5120
__global__ __launch_bounds__(256, 2) void k2_mma(const float* __restrict__ Adj) {
    extern __shared__ __align__(16) char sm[];
    const int t = threadIdx.x, lane = t & 31, w = t >> 5;
    const uint32_t sb = smem_u32(sm);
    const int i0 = blockIdx.x * 128, ubase0 = blockIdx.y * 3360;
    const int m0 = (w >> 1) * 32, n0 = (w & 1) * 32;
    const uint32_t aofft = (uint32_t)((lane & 7) + ((lane >> 4) << 3)) * 272
                         + (uint32_t)(m0 + (((lane >> 3) & 1) << 3)) * 2;
    const uint32_t boff = (uint32_t)(n0 + (lane & 15)) * 80 + ((lane >> 4) << 4);
    const int brow = t >> 2, bc8 = (t & 3) << 3;

    float acc[2][4][4];
#pragma unroll
    for (int a = 0; a < 2; a++)
#pragma unroll
        for (int b = 0; b < 4; b++)
#pragma unroll
            for (int cc = 0; cc < 4; cc++) acc[a][b][cc] = 0.f;

    float2 ar[8]; uint4 b4h, b4l;

    auto LDGf = [&](int c) {
        const int ub = ubase0 + c * 32;
#pragma unroll
        for (int q = 0; q < 8; q++) {
            int pidx = t + q * 256;
            int aul = pidx >> 6, i2 = (pidx & 63) << 1;
            int gu = ub + aul;
            ar[q] = (gu < UD) ? *(const float2*)(Adj + (size_t)gu * ID + i0 + i2)
                              : make_float2(0.f, 0.f);
        }
        b4h = *(const uint4*)(g_uT_h + (size_t)brow * UPAD + ub + bc8);
        b4l = *(const uint4*)(g_uT_l + (size_t)brow * UPAD + ub + bc8);
    };
    auto STSf = [&](int b) {
        char* ab = sm + b * 8704;
        char* al = sm + 17408 + b * 8704;
#pragma unroll
        for (int q = 0; q < 8; q++) {
            int pidx = t + q * 256;
            int aul = pidx >> 6, i2 = (pidx & 63) << 1;
            uint32_t h, l; split2(ar[q].x, ar[q].y, h, l);
            *(uint32_t*)(ab + aul * 272 + i2 * 2) = h;
            *(uint32_t*)(al + aul * 272 + i2 * 2) = l;
        }
        *(uint4*)(sm + 34816 + b * 5120 + brow * 80 + ((t & 3) << 4)) = b4h;
        *(uint4*)(sm + 45056 + b * 5120 + brow * 80 + ((t & 3) << 4)) = b4l;
    };

    LDGf(0);
    STSf(0);
    __syncthreads();

    for (int c = 0; c < 105; c++) {
        const int b = c & 1;
        if (c + 1 < 105) LDGf(c + 1);
        const uint32_t bah = sb + b * 8704,         bal = sb + 17408 + b * 8704;
        const uint32_t bbh = sb + 34816 + b * 5120, bbl = sb + 45056 + b * 5120;
#pragma unroll
        for (int ks = 0; ks < 2; ks++) {
            uint32_t bh[2][4], bl[2][4], ah[2][4], al[2][4];
#pragma unroll
            for (int p = 0; p < 2; p++) {
                ldm4(bh[p], bbh + boff + p * 1280 + ks * 32);
                ldm4(bl[p], bbl + boff + p * 1280 + ks * 32);
            }
#pragma unroll
            for (int mi = 0; mi < 2; mi++) {
                ldm4t(ah[mi], bah + aofft + mi * 32 + ks * 4352);
                ldm4t(al[mi], bal + aofft + mi * 32 + ks * 4352);
            }
            // pass-major: RAW distance 8
#pragma unroll
            for (int mi = 0; mi < 2; mi++)
#pragma unroll
                for (int nt = 0; nt < 4; nt++) {
                    int p = nt >> 1, j = nt & 1;
                    mma_bf16(acc[mi][nt], ah[mi], bh[p][j], bh[p][j + 2]);
                }
#pragma unroll
            for (int mi = 0; mi < 2; mi++)
#pragma unroll
                for (int nt = 0; nt < 4; nt++) {
                    int p = nt >> 1, j = nt & 1;
                    mma_bf16(acc[mi][nt], ah[mi], bl[p][j], bl[p][j + 2]);
                }
#pragma unroll
            for (int mi = 0; mi < 2; mi++)
#pragma unroll
                for (int nt = 0; nt < 4; nt++) {
                    int p = nt >> 1, j = nt & 1;
                    mma_bf16(acc[mi][nt], al[mi], bh[p][j], bh[p][j + 2]);
                }
        }
        if (c + 1 < 105) STSf(b ^ 1);
        __syncthreads();
    }

    float* dst = g_rp[blockIdx.y];
    const int g = lane >> 2, tg = lane & 3;
#pragma unroll
    for (int mi = 0; mi < 2; mi++)
#pragma unroll
        for (int nt = 0; nt < 4; nt++) {
            int row = i0 + m0 + mi * 16 + g;
            int col = n0 + nt * 8 + tg * 2;
            if (row < ID)     *(float2*)(dst + (size_t)row * 64 + col)       = make_float2(acc[mi][nt][0], acc[mi][nt][1]);
            if (row + 8 < ID) *(float2*)(dst + (size_t)(row + 8) * 64 + col) = make_float2(acc[mi][nt][2], acc[mi][nt][3]);
        }
}

// ---------------- reductions + bf16 split ----------------
__global__ __launch_bounds__(256) void red_l(const float* __restrict__ lam) {
    int idx = blockIdx.x * 256 + threadIdx.x;
    if (idx >= UPAD * 64) return;
    int u = idx >> 6;
    float v = 0.f;
    if (u < UD) v = (g_lp[0][idx] + g_lp[1][idx] + g_lp[2][idx]) / lam[idx & 63];
    split1(v, g_l_h[idx], g_l_l[idx]);
}
__global__ __launch_bounds__(256) void red_r() {
    int idx = blockIdx.x * 256 + threadIdx.x;
    if (idx >= IPAD * 64) return;
    int i = idx >> 6;
    float v = 0.f;
    if (i < ID) v = g_rp[0][idx] + g_rp[1][idx] + g_rp[2][idx];
    split1(v, g_r_h[idx], g_r_l[idx]);
}

// ---------------- K3: out[u][i] = g_l @ g_r^T  (M=128u, N=128i, K=64 single pass) ----------------
__global__ __launch_bounds__(256, 2) void k3_mma(float* __restrict__ out) {
    extern __shared__ __align__(16) char sm[];
    const int t = threadIdx.x, lane = t & 31, w = t >> 5;
    const uint32_t sb = smem_u32(sm);
    const int u0 = blockIdx.x * 128, i0 = blockIdx.y * 128;
    const int m0 = (w >> 2) * 64, n0 = (w & 3) * 32;
    const uint32_t abase = (uint32_t)(m0 + (lane & 15)) * 144 + ((lane >> 4) << 4);
    const uint32_t bbase = (uint32_t)(n0 + (lane & 15)) * 144 + ((lane >> 4) << 4);

#pragma unroll
    for (int q = 0; q < 4; q++) {
        int idx = t + q * 256;
        int row = idx >> 3, c8 = (idx & 7) << 3;
        *(uint4*)(sm + row * 144 + c8 * 2)         = *(const uint4*)(g_l_h + (size_t)(u0 + row) * 64 + c8);
        *(uint4*)(sm + 18432 + row * 144 + c8 * 2) = *(const uint4*)(g_l_l + (size_t)(u0 + row) * 64 + c8);
        *(uint4*)(sm + 36864 + row * 144 + c8 * 2) = *(const uint4*)(g_r_h + (size_t)(i0 + row) * 64 + c8);
        *(uint4*)(sm + 55296 + row * 144 + c8 * 2) = *(const uint4*)(g_r_l + (size_t)(i0 + row) * 64 + c8);
    }
    __syncthreads();

    float acc[4][4][4];
#pragma unroll
    for (int a = 0; a < 4; a++)
#pragma unroll
        for (int b = 0; b < 4; b++)
#pragma unroll
            for (int cc = 0; cc < 4; cc++) acc[a][b][cc] = 0.f;

#pragma unroll
    for (int ks = 0; ks < 4; ks++) {
        uint32_t bh[2][4], bl[2][4];
#pragma unroll
        for (int p = 0; p < 2; p++) {
            ldm4(bh[p], sb + 36864 + bbase + p * 2304 + ks * 32);
            ldm4(bl[p], sb + 55296 + bbase + p * 2304 + ks * 32);
        }
#pragma unroll
        for (int mi = 0; mi < 4; mi++) {
            uint32_t ah[4], al[4];
            ldm4(ah, sb + abase + mi * 2304 + ks * 32);
            ldm4(al, sb + 18432 + abase + mi * 2304 + ks * 32);
            // pass-major within mi: RAW distance 4
#pragma unroll
            for (int nt = 0; nt < 4; nt++) {
                int p = nt >> 1, j = nt & 1;
                mma_bf16(acc[mi][nt], ah, bh[p][j], bh[p][j + 2]);
            }
#pragma unroll
            for (int nt = 0; nt < 4; nt++) {
                int p = nt >> 1, j = nt & 1;
                mma_bf16(acc[mi][nt], ah, bl[p][j], bl[p][j + 2]);
            }
#pragma unroll
            for (int nt = 0; nt < 4; nt++) {
                int p = nt >> 1, j = nt & 1;
                mma_bf16(acc[mi][nt], al, bh[p][j], bh[p][j + 2]);
            }
        }
    }

    const int g = lane >> 2, tg = lane & 3;
#pragma unroll
    for (int mi = 0; mi < 4; mi++)
#pragma unroll
        for (int nt = 0; nt < 4; nt++) {
            int row = u0 + m0 + mi * 16 + g;
            int col = i0 + n0 + nt * 8 + tg * 2;
            if (col < ID) {
                if (row < UD)     *(float2*)(out + (size_t)row * ID + col)       = make_float2(acc[mi][nt][0], acc[mi][nt][1]);
                if (row + 8 < UD) *(float2*)(out + (size_t)(row + 8) * ID + col) = make_float2(acc[mi][nt][2], acc[mi][nt][3]);
            }
        }
}

// ---------------- launch ----------------
extern "C" void kernel_launch(void* const* d_in, const int* in_sizes, int n_in,
                              void* d_out, int out_size) {
    const float* lambda_mat = (const float*)d_in[0];
    const float* user_sv    = (const float*)d_in[1];
    const float* item_sv    = (const float*)d_in[2];
    const float* adj_mat    = (const float*)d_in[3];
    const float* norm_adj   = (const float*)d_in[4];
    float* out = (float*)d_out;

    cudaFuncSetAttribute(k1_mma, cudaFuncAttributeMaxDynamicSharedMemorySize, 61440);
    cudaFuncSetAttribute(k2_mma, cudaFuncAttributeMaxDynamicSharedMemorySize, 55296);
    cudaFuncSetAttribute(k3_mma, cudaFuncAttributeMaxDynamicSharedMemorySize, 73728);

    p_item<<<IPAD / 64, 256>>>(item_sv);
    p_user<<<UPAD / 64, 256>>>(user_sv);
    k1_mma<<<dim3(79, 3), 256, 61440>>>(norm_adj);
    k2_mma<<<dim3(94, 3), 256, 55296>>>(adj_mat);
    red_l<<<(UPAD * 64) / 256, 256>>>(lambda_mat);
    red_r<<<(IPAD * 64) / 256, 256>>>();
    k3_mma<<<dim3(79, 94), 256, 73728>>>(out);
}

// round 10
// speedup vs baseline: 1.3750x; 1.3078x over previous
#include <cuda_runtime.h>
#include <cuda_fp16.h>
#include <cstdint>

#define UD 10000
#define ID 12000
#define IPAD 12032   // 94*128
#define UPAD 10112   // 79*128

// ---------------- scratch ----------------
__device__ __align__(16) uint16_t g_iT_h[64 * IPAD], g_iT_l[64 * IPAD];  // item_sv^T fp16 hi/lo [k][i]
__device__ __align__(16) uint16_t g_uT_h[64 * UPAD], g_uT_l[64 * UPAD];  // user_sv^T fp16 hi/lo [k][u]
__device__ __align__(16) float    g_lp[3][(size_t)UD * 64];              // K1 partials [u][k]
__device__ __align__(16) float    g_rp[3][(size_t)ID * 64];              // K2 partials [i][k]
__device__ __align__(16) uint16_t g_l_h[UPAD * 64];                      // left*invL fp16 [u][k] (single)
__device__ __align__(16) uint16_t g_r_h[IPAD * 64], g_r_l[IPAD * 64];    // right^T fp16 hi/lo [i][k]

// ---------------- helpers ----------------
__device__ __forceinline__ uint32_t smem_u32(const void* p) {
    uint32_t a;
    asm("{ .reg .u64 t; cvta.to.shared.u64 t, %1; cvt.u32.u64 %0, t; }" : "=r"(a) : "l"(p));
    return a;
}
// pack two floats -> fp16x2 (x0 in low half)
__device__ __forceinline__ uint32_t packh2(float x0, float x1) {
    uint32_t r;
    asm("cvt.rn.f16x2.f32 %0, %1, %2;" : "=r"(r) : "f"(x1), "f"(x0));
    return r;
}
// fp16 hi + residual lo for one float
__device__ __forceinline__ void split1h(float x, uint16_t& h, uint16_t& l) {
    __half hh = __float2half_rn(x);
    float r = x - __half2float(hh);
    h = __half_as_ushort(hh);
    l = __half_as_ushort(__float2half_rn(r));
}
__device__ __forceinline__ void ldm4(uint32_t* r, uint32_t a) {
    asm volatile("ldmatrix.sync.aligned.m8n8.x4.shared.b16 {%0,%1,%2,%3},[%4];"
                 : "=r"(r[0]), "=r"(r[1]), "=r"(r[2]), "=r"(r[3]) : "r"(a));
}
__device__ __forceinline__ void ldm4t(uint32_t* r, uint32_t a) {
    asm volatile("ldmatrix.sync.aligned.m8n8.x4.trans.shared.b16 {%0,%1,%2,%3},[%4];"
                 : "=r"(r[0]), "=r"(r[1]), "=r"(r[2]), "=r"(r[3]) : "r"(a));
}
__device__ __forceinline__ void mma_f16(float* d, const uint32_t* a, uint32_t b0, uint32_t b1) {
    asm volatile("mma.sync.aligned.m16n8k16.row.col.f32.f16.f16.f32 "
                 "{%0,%1,%2,%3},{%4,%5,%6,%7},{%8,%9},{%0,%1,%2,%3};"
                 : "+f"(d[0]), "+f"(d[1]), "+f"(d[2]), "+f"(d[3])
                 : "r"(a[0]), "r"(a[1]), "r"(a[2]), "r"(a[3]), "r"(b0), "r"(b1));
}

// ---------------- prep: tiled transpose + fp16 split ----------------
__global__ __launch_bounds__(256) void p_item(const float* __restrict__ isv) {
    __shared__ float st[64][65];
    const int t = threadIdx.x, i0 = blockIdx.x * 64;
#pragma unroll
    for (int q = 0; q < 16; q++) {
        int idx = t + q * 256;
        int il = idx >> 6, k = idx & 63, gi = i0 + il;
        st[il][k] = (gi < ID) ? isv[(size_t)gi * 64 + k] : 0.f;
    }
    __syncthreads();
#pragma unroll
    for (int q = 0; q < 16; q++) {
        int idx = t + q * 256;
        int k = idx >> 6, il = idx & 63;
        uint16_t h, l; split1h(st[il][k], h, l);
        g_iT_h[(size_t)k * IPAD + i0 + il] = h;
        g_iT_l[(size_t)k * IPAD + i0 + il] = l;
    }
}
__global__ __launch_bounds__(256) void p_user(const float* __restrict__ usv) {
    __shared__ float st[64][65];
    const int t = threadIdx.x, u0 = blockIdx.x * 64;
#pragma unroll
    for (int q = 0; q < 16; q++) {
        int idx = t + q * 256;
        int ul = idx >> 6, k = idx & 63, gu = u0 + ul;
        st[ul][k] = (gu < UD) ? usv[(size_t)gu * 64 + k] : 0.f;
    }
    __syncthreads();
#pragma unroll
    for (int q = 0; q < 16; q++) {
        int idx = t + q * 256;
        int k = idx >> 6, ul = idx & 63;
        uint16_t h, l; split1h(st[ul][k], h, l);
        g_uT_h[(size_t)k * UPAD + u0 + ul] = h;
        g_uT_l[(size_t)k * UPAD + u0 + ul] = l;
    }
}

// ---------------- K1: g_lp[s] = norm_adj @ item_sv  (M=128u, N=64k, Kchunk=32i, 2-buf) ----------
// dyn smem 40960: Ah[b] @ b*10240, Bh[b] @ 20480+b*5120, Bl[b] @ 30720+b*5120  (pitch 80)
__global__ __launch_bounds__(256, 2) void k1_mma(const float* __restrict__ A) {
    extern __shared__ __align__(16) char sm[];
    const int t = threadIdx.x, lane = t & 31, w = t >> 5;
    const uint32_t sb = smem_u32(sm);
    const int u0 = blockIdx.x * 128, ibase0 = blockIdx.y * 4000;
    const int m0 = (w >> 1) * 32, n0 = (w & 1) * 32;
    const uint32_t aoff = (uint32_t)(m0 + (lane & 15)) * 80 + ((lane >> 4) << 4);
    const uint32_t boff = (uint32_t)(n0 + (lane & 15)) * 80 + ((lane >> 4) << 4);
    const int brow = t >> 2, bc8 = (t & 3) << 3;

    float acc[2][4][4];
#pragma unroll
    for (int a = 0; a < 2; a++)
#pragma unroll
        for (int b = 0; b < 4; b++)
#pragma unroll
            for (int cc = 0; cc < 4; cc++) acc[a][b][cc] = 0.f;

    float2 ar[8]; uint4 b4h, b4l;

    auto LDGf = [&](int c) {
        const int ib = ibase0 + c * 32;
#pragma unroll
        for (int q = 0; q < 8; q++) {
            int pidx = t + q * 256;
            int aul = pidx >> 4, ic2 = (pidx & 15) << 1;
            int gu = u0 + aul;
            ar[q] = (gu < UD) ? *(const float2*)(A + (size_t)gu * ID + ib + ic2)
                              : make_float2(0.f, 0.f);
        }
        b4h = *(const uint4*)(g_iT_h + (size_t)brow * IPAD + ib + bc8);
        b4l = *(const uint4*)(g_iT_l + (size_t)brow * IPAD + ib + bc8);
    };
    auto STSf = [&](int b) {
        char* ab = sm + b * 10240;
#pragma unroll
        for (int q = 0; q < 8; q++) {
            int pidx = t + q * 256;
            int aul = pidx >> 4, ic2 = (pidx & 15) << 1;
            *(uint32_t*)(ab + aul * 80 + ic2 * 2) = packh2(ar[q].x, ar[q].y);
        }
        *(uint4*)(sm + 20480 + b * 5120 + brow * 80 + ((t & 3) << 4)) = b4h;
        *(uint4*)(sm + 30720 + b * 5120 + brow * 80 + ((t & 3) << 4)) = b4l;
    };

    LDGf(0);
    STSf(0);
    __syncthreads();

    for (int c = 0; c < 125; c++) {
        const int b = c & 1;
        if (c + 1 < 125) LDGf(c + 1);
        const uint32_t bah = sb + b * 10240;
        const uint32_t bbh = sb + 20480 + b * 5120, bbl = sb + 30720 + b * 5120;
#pragma unroll
        for (int ks = 0; ks < 2; ks++) {
            uint32_t bh[2][4], bl[2][4], ah[2][4];
#pragma unroll
            for (int p = 0; p < 2; p++) {
                ldm4(bh[p], bbh + boff + p * 1280 + ks * 32);
                ldm4(bl[p], bbl + boff + p * 1280 + ks * 32);
            }
#pragma unroll
            for (int mi = 0; mi < 2; mi++)
                ldm4(ah[mi], bah + aoff + mi * 1280 + ks * 32);
            // pass 1: A*Bh ; pass 2: A*Bl
#pragma unroll
            for (int mi = 0; mi < 2; mi++)
#pragma unroll
                for (int nt = 0; nt < 4; nt++) {
                    int p = nt >> 1, j = nt & 1;
                    mma_f16(acc[mi][nt], ah[mi], bh[p][j], bh[p][j + 2]);
                }
#pragma unroll
            for (int mi = 0; mi < 2; mi++)
#pragma unroll
                for (int nt = 0; nt < 4; nt++) {
                    int p = nt >> 1, j = nt & 1;
                    mma_f16(acc[mi][nt], ah[mi], bl[p][j], bl[p][j + 2]);
                }
        }
        if (c + 1 < 125) STSf(b ^ 1);
        __syncthreads();
    }

    float* dst = g_lp[blockIdx.y];
    const int g = lane >> 2, tg = lane & 3;
#pragma unroll
    for (int mi = 0; mi < 2; mi++)
#pragma unroll
        for (int nt = 0; nt < 4; nt++) {
            int row = u0 + m0 + mi * 16 + g;
            int col = n0 + nt * 8 + tg * 2;
            if (row < UD)     *(float2*)(dst + (size_t)row * 64 + col)       = make_float2(acc[mi][nt][0], acc[mi][nt][1]);
            if (row + 8 < UD) *(float2*)(dst + (size_t)(row + 8) * 64 + col) = make_float2(acc[mi][nt][2], acc[mi][nt][3]);
        }
}

// ---------------- K2: g_rp[s][i][k] = adj^T @ user_sv  (M=128i, N=64k, Kchunk=32u, 2-buf) --------
// dyn smem 37888: Ah[b] @ b*8704 (pitch 272), Bh[b] @ 17408+b*5120, Bl[b] @ 27648+b*5120
__global__ __launch_bounds__(256, 2) void k2_mma(const float* __restrict__ Adj) {
    extern __shared__ __align__(16) char sm[];
    const int t = threadIdx.x, lane = t & 31, w = t >> 5;
    const uint32_t sb = smem_u32(sm);
    const int i0 = blockIdx.x * 128, ubase0 = blockIdx.y * 3360;
    const int m0 = (w >> 1) * 32, n0 = (w & 1) * 32;
    const uint32_t aofft = (uint32_t)((lane & 7) + ((lane >> 4) << 3)) * 272
                         + (uint32_t)(m0 + (((lane >> 3) & 1) << 3)) * 2;
    const uint32_t boff = (uint32_t)(n0 + (lane & 15)) * 80 + ((lane >> 4) << 4);
    const int brow = t >> 2, bc8 = (t & 3) << 3;

    float acc[2][4][4];
#pragma unroll
    for (int a = 0; a < 2; a++)
#pragma unroll
        for (int b = 0; b < 4; b++)
#pragma unroll
            for (int cc = 0; cc < 4; cc++) acc[a][b][cc] = 0.f;

    float2 ar[8]; uint4 b4h, b4l;

    auto LDGf = [&](int c) {
        const int ub = ubase0 + c * 32;
#pragma unroll
        for (int q = 0; q < 8; q++) {
            int pidx = t + q * 256;
            int aul = pidx >> 6, i2 = (pidx & 63) << 1;
            int gu = ub + aul;
            ar[q] = (gu < UD) ? *(const float2*)(Adj + (size_t)gu * ID + i0 + i2)
                              : make_float2(0.f, 0.f);
        }
        b4h = *(const uint4*)(g_uT_h + (size_t)brow * UPAD + ub + bc8);
        b4l = *(const uint4*)(g_uT_l + (size_t)brow * UPAD + ub + bc8);
    };
    auto STSf = [&](int b) {
        char* ab = sm + b * 8704;
#pragma unroll
        for (int q = 0; q < 8; q++) {
            int pidx = t + q * 256;
            int aul = pidx >> 6, i2 = (pidx & 63) << 1;
            *(uint32_t*)(ab + aul * 272 + i2 * 2) = packh2(ar[q].x, ar[q].y);
        }
        *(uint4*)(sm + 17408 + b * 5120 + brow * 80 + ((t & 3) << 4)) = b4h;
        *(uint4*)(sm + 27648 + b * 5120 + brow * 80 + ((t & 3) << 4)) = b4l;
    };

    LDGf(0);
    STSf(0);
    __syncthreads();

    for (int c = 0; c < 105; c++) {
        const int b = c & 1;
        if (c + 1 < 105) LDGf(c + 1);
        const uint32_t bah = sb + b * 8704;
        const uint32_t bbh = sb + 17408 + b * 5120, bbl = sb + 27648 + b * 5120;
#pragma unroll
        for (int ks = 0; ks < 2; ks++) {
            uint32_t bh[2][4], bl[2][4], ah[2][4];
#pragma unroll
            for (int p = 0; p < 2; p++) {
                ldm4(bh[p], bbh + boff + p * 1280 + ks * 32);
                ldm4(bl[p], bbl + boff + p * 1280 + ks * 32);
            }
#pragma unroll
            for (int mi = 0; mi < 2; mi++)
                ldm4t(ah[mi], bah + aofft + mi * 32 + ks * 4352);
#pragma unroll
            for (int mi = 0; mi < 2; mi++)
#pragma unroll
                for (int nt = 0; nt < 4; nt++) {
                    int p = nt >> 1, j = nt & 1;
                    mma_f16(acc[mi][nt], ah[mi], bh[p][j], bh[p][j + 2]);
                }
#pragma unroll
            for (int mi = 0; mi < 2; mi++)
#pragma unroll
                for (int nt = 0; nt < 4; nt++) {
                    int p = nt >> 1, j = nt & 1;
                    mma_f16(acc[mi][nt], ah[mi], bl[p][j], bl[p][j + 2]);
                }
        }
        if (c + 1 < 105) STSf(b ^ 1);
        __syncthreads();
    }

    float* dst = g_rp[blockIdx.y];
    const int g = lane >> 2, tg = lane & 3;
#pragma unroll
    for (int mi = 0; mi < 2; mi++)
#pragma unroll
        for (int nt = 0; nt < 4; nt++) {
            int row = i0 + m0 + mi * 16 + g;
            int col = n0 + nt * 8 + tg * 2;
            if (row < ID)     *(float2*)(dst + (size_t)row * 64 + col)       = make_float2(acc[mi][nt][0], acc[mi][nt][1]);
            if (row + 8 < ID) *(float2*)(dst + (size_t)(row + 8) * 64 + col) = make_float2(acc[mi][nt][2], acc[mi][nt][3]);
        }
}

// ---------------- reductions + fp16 pack/split ----------------
__global__ __launch_bounds__(256) void red_l(const float* __restrict__ lam) {
    int idx = blockIdx.x * 256 + threadIdx.x;
    if (idx >= UPAD * 64) return;
    int u = idx >> 6;
    float v = 0.f;
    if (u < UD) v = (g_lp[0][idx] + g_lp[1][idx] + g_lp[2][idx]) / lam[idx & 63];
    g_l_h[idx] = __half_as_ushort(__float2half_rn(v));
}
__global__ __launch_bounds__(256) void red_r() {
    int idx = blockIdx.x * 256 + threadIdx.x;
    if (idx >= IPAD * 64) return;
    int i = idx >> 6;
    float v = 0.f;
    if (i < ID) v = g_rp[0][idx] + g_rp[1][idx] + g_rp[2][idx];
    uint16_t h, l; split1h(v, h, l);
    g_r_h[idx] = h; g_r_l[idx] = l;
}

// ---------------- K3: out[u][i] = g_l @ g_r^T  (M=128u, N=128i, K=64, 2-pass) --------------------
// dyn smem 55296: A(g_l) @0, Bh @18432, Bl @36864  (pitch 144)
__global__ __launch_bounds__(256, 2) void k3_mma(float* __restrict__ out) {
    extern __shared__ __align__(16) char sm[];
    const int t = threadIdx.x, lane = t & 31, w = t >> 5;
    const uint32_t sb = smem_u32(sm);
    const int u0 = blockIdx.x * 128, i0 = blockIdx.y * 128;
    const int m0 = (w >> 2) * 64, n0 = (w & 3) * 32;
    const uint32_t abase = (uint32_t)(m0 + (lane & 15)) * 144 + ((lane >> 4) << 4);
    const uint32_t bbase = (uint32_t)(n0 + (lane & 15)) * 144 + ((lane >> 4) << 4);

#pragma unroll
    for (int q = 0; q < 4; q++) {
        int idx = t + q * 256;
        int row = idx >> 3, c8 = (idx & 7) << 3;
        *(uint4*)(sm + row * 144 + c8 * 2)         = *(const uint4*)(g_l_h + (size_t)(u0 + row) * 64 + c8);
        *(uint4*)(sm + 18432 + row * 144 + c8 * 2) = *(const uint4*)(g_r_h + (size_t)(i0 + row) * 64 + c8);
        *(uint4*)(sm + 36864 + row * 144 + c8 * 2) = *(const uint4*)(g_r_l + (size_t)(i0 + row) * 64 + c8);
    }
    __syncthreads();

    float acc[4][4][4];
#pragma unroll
    for (int a = 0; a < 4; a++)
#pragma unroll
        for (int b = 0; b < 4; b++)
#pragma unroll
            for (int cc = 0; cc < 4; cc++) acc[a][b][cc] = 0.f;

#pragma unroll
    for (int ks = 0; ks < 4; ks++) {
        uint32_t bh[2][4], bl[2][4];
#pragma unroll
        for (int p = 0; p < 2; p++) {
            ldm4(bh[p], sb + 18432 + bbase + p * 2304 + ks * 32);
            ldm4(bl[p], sb + 36864 + bbase + p * 2304 + ks * 32);
        }
#pragma unroll
        for (int mi = 0; mi < 4; mi++) {
            uint32_t ah[4];
            ldm4(ah, sb + abase + mi * 2304 + ks * 32);
#pragma unroll
            for (int nt = 0; nt < 4; nt++) {
                int p = nt >> 1, j = nt & 1;
                mma_f16(acc[mi][nt], ah, bh[p][j], bh[p][j + 2]);
            }
#pragma unroll
            for (int nt = 0; nt < 4; nt++) {
                int p = nt >> 1, j = nt & 1;
                mma_f16(acc[mi][nt], ah, bl[p][j], bl[p][j + 2]);
            }
        }
    }

    const int g = lane >> 2, tg = lane & 3;
#pragma unroll
    for (int mi = 0; mi < 4; mi++)
#pragma unroll
        for (int nt = 0; nt < 4; nt++) {
            int row = u0 + m0 + mi * 16 + g;
            int col = i0 + n0 + nt * 8 + tg * 2;
            if (col < ID) {
                if (row < UD)     *(float2*)(out + (size_t)row * ID + col)       = make_float2(acc[mi][nt][0], acc[mi][nt][1]);
                if (row + 8 < UD) *(float2*)(out + (size_t)(row + 8) * ID + col) = make_float2(acc[mi][nt][2], acc[mi][nt][3]);
            }
        }
}

// ---------------- launch ----------------
extern "C" void kernel_launch(void* const* d_in, const int* in_sizes, int n_in,
                              void* d_out, int out_size) {
    const float* lambda_mat = (const float*)d_in[0];
    const float* user_sv    = (const float*)d_in[1];
    const float* item_sv    = (const float*)d_in[2];
    const float* adj_mat    = (const float*)d_in[3];
    const float* norm_adj   = (const float*)d_in[4];
    float* out = (float*)d_out;

    cudaFuncSetAttribute(k1_mma, cudaFuncAttributeMaxDynamicSharedMemorySize, 40960);
    cudaFuncSetAttribute(k2_mma, cudaFuncAttributeMaxDynamicSharedMemorySize, 37888);
    cudaFuncSetAttribute(k3_mma, cudaFuncAttributeMaxDynamicSharedMemorySize, 55296);

    p_item<<<IPAD / 64, 256>>>(item_sv);
    p_user<<<UPAD / 64, 256>>>(user_sv);
    k1_mma<<<dim3(79, 3), 256, 40960>>>(norm_adj);
    k2_mma<<<dim3(94, 3), 256, 37888>>>(adj_mat);
    red_l<<<(UPAD * 64) / 256, 256>>>(lambda_mat);
    red_r<<<(IPAD * 64) / 256, 256>>>();
    k3_mma<<<dim3(79, 94), 256, 55296>>>(out);
}

// round 11
// speedup vs baseline: 1.5153x; 1.1020x over previous
#include <cuda_runtime.h>
#include <cuda_fp16.h>
#include <cstdint>

#define UD 10000
#define ID 12000
#define IPAD 12032   // 94*128
#define UPAD 10112   // 79*128

// ---------------- scratch ----------------
__device__ __align__(16) uint16_t g_iT_h[64 * IPAD];                 // item_sv^T fp16 [k][i]
__device__ __align__(16) uint16_t g_uT_h[64 * UPAD];                 // user_sv^T fp16 [k][u]
__device__ __align__(16) float    g_lp[3][(size_t)UD * 64];          // K1 partials [u][k]
__device__ __align__(16) float    g_rp[3][(size_t)ID * 64];          // K2 partials [i][k]
__device__ __align__(16) uint16_t g_l_h[UPAD * 64];                  // left*invL fp16 [u][k]
__device__ __align__(16) uint16_t g_r_h[IPAD * 64];                  // right^T fp16 [i][k]

// ---------------- helpers ----------------
__device__ __forceinline__ uint32_t smem_u32(const void* p) {
    uint32_t a;
    asm("{ .reg .u64 t; cvta.to.shared.u64 t, %1; cvt.u32.u64 %0, t; }" : "=r"(a) : "l"(p));
    return a;
}
__device__ __forceinline__ uint32_t packh2(float x0, float x1) {
    uint32_t r;
    asm("cvt.rn.f16x2.f32 %0, %1, %2;" : "=r"(r) : "f"(x1), "f"(x0));
    return r;
}
__device__ __forceinline__ void ldm4(uint32_t* r, uint32_t a) {
    asm volatile("ldmatrix.sync.aligned.m8n8.x4.shared.b16 {%0,%1,%2,%3},[%4];"
                 : "=r"(r[0]), "=r"(r[1]), "=r"(r[2]), "=r"(r[3]) : "r"(a));
}
__device__ __forceinline__ void ldm4t(uint32_t* r, uint32_t a) {
    asm volatile("ldmatrix.sync.aligned.m8n8.x4.trans.shared.b16 {%0,%1,%2,%3},[%4];"
                 : "=r"(r[0]), "=r"(r[1]), "=r"(r[2]), "=r"(r[3]) : "r"(a));
}
__device__ __forceinline__ void mma_f16(float* d, const uint32_t* a, uint32_t b0, uint32_t b1) {
    asm volatile("mma.sync.aligned.m16n8k16.row.col.f32.f16.f16.f32 "
                 "{%0,%1,%2,%3},{%4,%5,%6,%7},{%8,%9},{%0,%1,%2,%3};"
                 : "+f"(d[0]), "+f"(d[1]), "+f"(d[2]), "+f"(d[3])
                 : "r"(a[0]), "r"(a[1]), "r"(a[2]), "r"(a[3]), "r"(b0), "r"(b1));
}

// ---------------- prep: tiled transpose + fp16 ----------------
__global__ __launch_bounds__(256) void p_item(const float* __restrict__ isv) {
    __shared__ float st[64][65];
    const int t = threadIdx.x, i0 = blockIdx.x * 64;
#pragma unroll
    for (int q = 0; q < 16; q++) {
        int idx = t + q * 256;
        int il = idx >> 6, k = idx & 63, gi = i0 + il;
        st[il][k] = (gi < ID) ? isv[(size_t)gi * 64 + k] : 0.f;
    }
    __syncthreads();
#pragma unroll
    for (int q = 0; q < 16; q++) {
        int idx = t + q * 256;
        int k = idx >> 6, il = idx & 63;
        g_iT_h[(size_t)k * IPAD + i0 + il] = __half_as_ushort(__float2half_rn(st[il][k]));
    }
}
__global__ __launch_bounds__(256) void p_user(const float* __restrict__ usv) {
    __shared__ float st[64][65];
    const int t = threadIdx.x, u0 = blockIdx.x * 64;
#pragma unroll
    for (int q = 0; q < 16; q++) {
        int idx = t + q * 256;
        int ul = idx >> 6, k = idx & 63, gu = u0 + ul;
        st[ul][k] = (gu < UD) ? usv[(size_t)gu * 64 + k] : 0.f;
    }
    __syncthreads();
#pragma unroll
    for (int q = 0; q < 16; q++) {
        int idx = t + q * 256;
        int k = idx >> 6, ul = idx & 63;
        g_uT_h[(size_t)k * UPAD + u0 + ul] = __half_as_ushort(__float2half_rn(st[ul][k]));
    }
}

// ---------------- K1: g_lp[s] = norm_adj @ item_sv  (M=128u, N=64k, Kchunk=32i, 2-buf) ----------
// dyn smem 30720: A[b] @ b*10240, B[b] @ 20480+b*5120  (pitch 80)
__global__ __launch_bounds__(256, 2) void k1_mma(const float* __restrict__ A) {
    extern __shared__ __align__(16) char sm[];
    const int t = threadIdx.x, lane = t & 31, w = t >> 5;
    const uint32_t sb = smem_u32(sm);
    const int u0 = blockIdx.x * 128, ibase0 = blockIdx.y * 4000;
    const int m0 = (w >> 1) * 32, n0 = (w & 1) * 32;
    const uint32_t aoff = (uint32_t)(m0 + (lane & 15)) * 80 + ((lane >> 4) << 4);
    const uint32_t boff = (uint32_t)(n0 + (lane & 15)) * 80 + ((lane >> 4) << 4);
    const int brow = t >> 2, bc8 = (t & 3) << 3;

    float acc[2][4][4];
#pragma unroll
    for (int a = 0; a < 2; a++)
#pragma unroll
        for (int b = 0; b < 4; b++)
#pragma unroll
            for (int cc = 0; cc < 4; cc++) acc[a][b][cc] = 0.f;

    float2 ar[8]; uint4 b4h;

    auto LDGf = [&](int c) {
        const int ib = ibase0 + c * 32;
#pragma unroll
        for (int q = 0; q < 8; q++) {
            int pidx = t + q * 256;
            int aul = pidx >> 4, ic2 = (pidx & 15) << 1;
            int gu = u0 + aul;
            ar[q] = (gu < UD) ? *(const float2*)(A + (size_t)gu * ID + ib + ic2)
                              : make_float2(0.f, 0.f);
        }
        b4h = *(const uint4*)(g_iT_h + (size_t)brow * IPAD + ib + bc8);
    };
    auto STSf = [&](int b) {
        char* ab = sm + b * 10240;
#pragma unroll
        for (int q = 0; q < 8; q++) {
            int pidx = t + q * 256;
            int aul = pidx >> 4, ic2 = (pidx & 15) << 1;
            *(uint32_t*)(ab + aul * 80 + ic2 * 2) = packh2(ar[q].x, ar[q].y);
        }
        *(uint4*)(sm + 20480 + b * 5120 + brow * 80 + ((t & 3) << 4)) = b4h;
    };

    LDGf(0);
    STSf(0);
    __syncthreads();

    for (int c = 0; c < 125; c++) {
        const int b = c & 1;
        if (c + 1 < 125) LDGf(c + 1);
        const uint32_t bah = sb + b * 10240;
        const uint32_t bbh = sb + 20480 + b * 5120;
#pragma unroll
        for (int ks = 0; ks < 2; ks++) {
            uint32_t bh[2][4], ah[2][4];
#pragma unroll
            for (int p = 0; p < 2; p++)
                ldm4(bh[p], bbh + boff + p * 1280 + ks * 32);
#pragma unroll
            for (int mi = 0; mi < 2; mi++)
                ldm4(ah[mi], bah + aoff + mi * 1280 + ks * 32);
#pragma unroll
            for (int mi = 0; mi < 2; mi++)
#pragma unroll
                for (int nt = 0; nt < 4; nt++) {
                    int p = nt >> 1, j = nt & 1;
                    mma_f16(acc[mi][nt], ah[mi], bh[p][j], bh[p][j + 2]);
                }
        }
        if (c + 1 < 125) STSf(b ^ 1);
        __syncthreads();
    }

    float* dst = g_lp[blockIdx.y];
    const int g = lane >> 2, tg = lane & 3;
#pragma unroll
    for (int mi = 0; mi < 2; mi++)
#pragma unroll
        for (int nt = 0; nt < 4; nt++) {
            int row = u0 + m0 + mi * 16 + g;
            int col = n0 + nt * 8 + tg * 2;
            if (row < UD)     *(float2*)(dst + (size_t)row * 64 + col)       = make_float2(acc[mi][nt][0], acc[mi][nt][1]);
            if (row + 8 < UD) *(float2*)(dst + (size_t)(row + 8) * 64 + col) = make_float2(acc[mi][nt][2], acc[mi][nt][3]);
        }
}

// ---------------- K2: g_rp[s][i][k] = adj^T @ user_sv  (M=128i, N=64k, Kchunk=32u, 2-buf) --------
// dyn smem 27648: A[b] @ b*8704 (pitch 272), B[b] @ 17408+b*5120  (pitch 80)
__global__ __launch_bounds__(256, 2) void k2_mma(const float* __restrict__ Adj) {
    extern __shared__ __align__(16) char sm[];
    const int t = threadIdx.x, lane = t & 31, w = t >> 5;
    const uint32_t sb = smem_u32(sm);
    const int i0 = blockIdx.x * 128, ubase0 = blockIdx.y * 3360;
    const int m0 = (w >> 1) * 32, n0 = (w & 1) * 32;
    const uint32_t aofft = (uint32_t)((lane & 7) + ((lane >> 4) << 3)) * 272
                         + (uint32_t)(m0 + (((lane >> 3) & 1) << 3)) * 2;
    const uint32_t boff = (uint32_t)(n0 + (lane & 15)) * 80 + ((lane >> 4) << 4);
    const int brow = t >> 2, bc8 = (t & 3) << 3;

    float acc[2][4][4];
#pragma unroll
    for (int a = 0; a < 2; a++)
#pragma unroll
        for (int b = 0; b < 4; b++)
#pragma unroll
            for (int cc = 0; cc < 4; cc++) acc[a][b][cc] = 0.f;

    float2 ar[8]; uint4 b4h;

    auto LDGf = [&](int c) {
        const int ub = ubase0 + c * 32;
#pragma unroll
        for (int q = 0; q < 8; q++) {
            int pidx = t + q * 256;
            int aul = pidx >> 6, i2 = (pidx & 63) << 1;
            int gu = ub + aul;
            ar[q] = (gu < UD) ? *(const float2*)(Adj + (size_t)gu * ID + i0 + i2)
                              : make_float2(0.f, 0.f);
        }
        b4h = *(const uint4*)(g_uT_h + (size_t)brow * UPAD + ub + bc8);
    };
    auto STSf = [&](int b) {
        char* ab = sm + b * 8704;
#pragma unroll
        for (int q = 0; q < 8; q++) {
            int pidx = t + q * 256;
            int aul = pidx >> 6, i2 = (pidx & 63) << 1;
            *(uint32_t*)(ab + aul * 272 + i2 * 2) = packh2(ar[q].x, ar[q].y);
        }
        *(uint4*)(sm + 17408 + b * 5120 + brow * 80 + ((t & 3) << 4)) = b4h;
    };

    LDGf(0);
    STSf(0);
    __syncthreads();

    for (int c = 0; c < 105; c++) {
        const int b = c & 1;
        if (c + 1 < 105) LDGf(c + 1);
        const uint32_t bah = sb + b * 8704;
        const uint32_t bbh = sb + 17408 + b * 5120;
#pragma unroll
        for (int ks = 0; ks < 2; ks++) {
            uint32_t bh[2][4], ah[2][4];
#pragma unroll
            for (int p = 0; p < 2; p++)
                ldm4(bh[p], bbh + boff + p * 1280 + ks * 32);
#pragma unroll
            for (int mi = 0; mi < 2; mi++)
                ldm4t(ah[mi], bah + aofft + mi * 32 + ks * 4352);
#pragma unroll
            for (int mi = 0; mi < 2; mi++)
#pragma unroll
                for (int nt = 0; nt < 4; nt++) {
                    int p = nt >> 1, j = nt & 1;
                    mma_f16(acc[mi][nt], ah[mi], bh[p][j], bh[p][j + 2]);
                }
        }
        if (c + 1 < 105) STSf(b ^ 1);
        __syncthreads();
    }

    float* dst = g_rp[blockIdx.y];
    const int g = lane >> 2, tg = lane & 3;
#pragma unroll
    for (int mi = 0; mi < 2; mi++)
#pragma unroll
        for (int nt = 0; nt < 4; nt++) {
            int row = i0 + m0 + mi * 16 + g;
            int col = n0 + nt * 8 + tg * 2;
            if (row < ID)     *(float2*)(dst + (size_t)row * 64 + col)       = make_float2(acc[mi][nt][0], acc[mi][nt][1]);
            if (row + 8 < ID) *(float2*)(dst + (size_t)(row + 8) * 64 + col) = make_float2(acc[mi][nt][2], acc[mi][nt][3]);
        }
}

// ---------------- reductions + fp16 pack ----------------
__global__ __launch_bounds__(256) void red_l(const float* __restrict__ lam) {
    int idx = blockIdx.x * 256 + threadIdx.x;
    if (idx >= UPAD * 64) return;
    int u = idx >> 6;
    float v = 0.f;
    if (u < UD) v = (g_lp[0][idx] + g_lp[1][idx] + g_lp[2][idx]) / lam[idx & 63];
    g_l_h[idx] = __half_as_ushort(__float2half_rn(v));
}
__global__ __launch_bounds__(256) void red_r() {
    int idx = blockIdx.x * 256 + threadIdx.x;
    if (idx >= IPAD * 64) return;
    int i = idx >> 6;
    float v = 0.f;
    if (i < ID) v = g_rp[0][idx] + g_rp[1][idx] + g_rp[2][idx];
    g_r_h[idx] = __half_as_ushort(__float2half_rn(v));
}

// ---------------- K3: out[u][i] = g_l @ g_r^T  (M=128u, N=128i, K=64, single pass) ---------------
// dyn smem 36864: A(g_l) @0, B(g_r) @18432  (pitch 144)
__global__ __launch_bounds__(256, 2) void k3_mma(float* __restrict__ out) {
    extern __shared__ __align__(16) char sm[];
    const int t = threadIdx.x, lane = t & 31, w = t >> 5;
    const uint32_t sb = smem_u32(sm);
    const int u0 = blockIdx.x * 128, i0 = blockIdx.y * 128;
    const int m0 = (w >> 2) * 64, n0 = (w & 3) * 32;
    const uint32_t abase = (uint32_t)(m0 + (lane & 15)) * 144 + ((lane >> 4) << 4);
    const uint32_t bbase = (uint32_t)(n0 + (lane & 15)) * 144 + ((lane >> 4) << 4);

#pragma unroll
    for (int q = 0; q < 4; q++) {
        int idx = t + q * 256;
        int row = idx >> 3, c8 = (idx & 7) << 3;
        *(uint4*)(sm + row * 144 + c8 * 2)         = *(const uint4*)(g_l_h + (size_t)(u0 + row) * 64 + c8);
        *(uint4*)(sm + 18432 + row * 144 + c8 * 2) = *(const uint4*)(g_r_h + (size_t)(i0 + row) * 64 + c8);
    }
    __syncthreads();

    float acc[4][4][4];
#pragma unroll
    for (int a = 0; a < 4; a++)
#pragma unroll
        for (int b = 0; b < 4; b++)
#pragma unroll
            for (int cc = 0; cc < 4; cc++) acc[a][b][cc] = 0.f;

#pragma unroll
    for (int ks = 0; ks < 4; ks++) {
        uint32_t bh[2][4];
#pragma unroll
        for (int p = 0; p < 2; p++)
            ldm4(bh[p], sb + 18432 + bbase + p * 2304 + ks * 32);
#pragma unroll
        for (int mi = 0; mi < 4; mi++) {
            uint32_t ah[4];
            ldm4(ah, sb + abase + mi * 2304 + ks * 32);
#pragma unroll
            for (int nt = 0; nt < 4; nt++) {
                int p = nt >> 1, j = nt & 1;
                mma_f16(acc[mi][nt], ah, bh[p][j], bh[p][j + 2]);
            }
        }
    }

    const int g = lane >> 2, tg = lane & 3;
#pragma unroll
    for (int mi = 0; mi < 4; mi++)
#pragma unroll
        for (int nt = 0; nt < 4; nt++) {
            int row = u0 + m0 + mi * 16 + g;
            int col = i0 + n0 + nt * 8 + tg * 2;
            if (col < ID) {
                if (row < UD)     *(float2*)(out + (size_t)row * ID + col)       = make_float2(acc[mi][nt][0], acc[mi][nt][1]);
                if (row + 8 < UD) *(float2*)(out + (size_t)(row + 8) * ID + col) = make_float2(acc[mi][nt][2], acc[mi][nt][3]);
            }
        }
}

// ---------------- launch ----------------
extern "C" void kernel_launch(void* const* d_in, const int* in_sizes, int n_in,
                              void* d_out, int out_size) {
    const float* lambda_mat = (const float*)d_in[0];
    const float* user_sv    = (const float*)d_in[1];
    const float* item_sv    = (const float*)d_in[2];
    const float* adj_mat    = (const float*)d_in[3];
    const float* norm_adj   = (const float*)d_in[4];
    float* out = (float*)d_out;

    cudaFuncSetAttribute(k1_mma, cudaFuncAttributeMaxDynamicSharedMemorySize, 30720);
    cudaFuncSetAttribute(k2_mma, cudaFuncAttributeMaxDynamicSharedMemorySize, 27648);
    cudaFuncSetAttribute(k3_mma, cudaFuncAttributeMaxDynamicSharedMemorySize, 36864);

    p_item<<<IPAD / 64, 256>>>(item_sv);
    p_user<<<UPAD / 64, 256>>>(user_sv);
    k1_mma<<<dim3(79, 3), 256, 30720>>>(norm_adj);
    k2_mma<<<dim3(94, 3), 256, 27648>>>(adj_mat);
    red_l<<<(UPAD * 64) / 256, 256>>>(lambda_mat);
    red_r<<<(IPAD * 64) / 256, 256>>>();
    k3_mma<<<dim3(79, 94), 256, 36864>>>(out);
}

// round 12
// speedup vs baseline: 1.5508x; 1.0234x over previous
#include <cuda_runtime.h>
#include <cuda_fp16.h>
#include <cstdint>

#define UD 10000
#define ID 12000
#define IPAD 12032   // 94*128
#define UPAD 10112   // 79*128

// ---------------- scratch ----------------
__device__ __align__(16) uint16_t g_iT_h[64 * IPAD];                 // item_sv^T fp16 [k][i]
__device__ __align__(16) uint16_t g_uT_h[64 * UPAD];                 // user_sv^T fp16 [k][u]
__device__ __align__(16) float    g_lp[3][(size_t)UD * 64];          // K1 partials [u][k]
__device__ __align__(16) float    g_rp[3][(size_t)ID * 64];          // K2 partials [i][k]
__device__ __align__(16) uint16_t g_l_h[UPAD * 64];                  // left*invL fp16 [u][k]
__device__ __align__(16) uint16_t g_r_h[IPAD * 64];                  // right^T fp16 [i][k]

// ---------------- helpers ----------------
__device__ __forceinline__ uint32_t smem_u32(const void* p) {
    uint32_t a;
    asm("{ .reg .u64 t; cvta.to.shared.u64 t, %1; cvt.u32.u64 %0, t; }" : "=r"(a) : "l"(p));
    return a;
}
__device__ __forceinline__ uint32_t packh2(float x0, float x1) {
    uint32_t r;
    asm("cvt.rn.f16x2.f32 %0, %1, %2;" : "=r"(r) : "f"(x1), "f"(x0));
    return r;
}
__device__ __forceinline__ void ldm4(uint32_t* r, uint32_t a) {
    asm volatile("ldmatrix.sync.aligned.m8n8.x4.shared.b16 {%0,%1,%2,%3},[%4];"
                 : "=r"(r[0]), "=r"(r[1]), "=r"(r[2]), "=r"(r[3]) : "r"(a));
}
__device__ __forceinline__ void ldm4t(uint32_t* r, uint32_t a) {
    asm volatile("ldmatrix.sync.aligned.m8n8.x4.trans.shared.b16 {%0,%1,%2,%3},[%4];"
                 : "=r"(r[0]), "=r"(r[1]), "=r"(r[2]), "=r"(r[3]) : "r"(a));
}
__device__ __forceinline__ void mma_f16(float* d, const uint32_t* a, uint32_t b0, uint32_t b1) {
    asm volatile("mma.sync.aligned.m16n8k16.row.col.f32.f16.f16.f32 "
                 "{%0,%1,%2,%3},{%4,%5,%6,%7},{%8,%9},{%0,%1,%2,%3};"
                 : "+f"(d[0]), "+f"(d[1]), "+f"(d[2]), "+f"(d[3])
                 : "r"(a[0]), "r"(a[1]), "r"(a[2]), "r"(a[3]), "r"(b0), "r"(b1));
}

// ---------------- prep: tiled transpose + fp16 ----------------
__global__ __launch_bounds__(256) void p_item(const float* __restrict__ isv) {
    __shared__ float st[64][65];
    const int t = threadIdx.x, i0 = blockIdx.x * 64;
#pragma unroll
    for (int q = 0; q < 16; q++) {
        int idx = t + q * 256;
        int il = idx >> 6, k = idx & 63, gi = i0 + il;
        st[il][k] = (gi < ID) ? isv[(size_t)gi * 64 + k] : 0.f;
    }
    __syncthreads();
#pragma unroll
    for (int q = 0; q < 16; q++) {
        int idx = t + q * 256;
        int k = idx >> 6, il = idx & 63;
        g_iT_h[(size_t)k * IPAD + i0 + il] = __half_as_ushort(__float2half_rn(st[il][k]));
    }
}
__global__ __launch_bounds__(256) void p_user(const float* __restrict__ usv) {
    __shared__ float st[64][65];
    const int t = threadIdx.x, u0 = blockIdx.x * 64;
#pragma unroll
    for (int q = 0; q < 16; q++) {
        int idx = t + q * 256;
        int ul = idx >> 6, k = idx & 63, gu = u0 + ul;
        st[ul][k] = (gu < UD) ? usv[(size_t)gu * 64 + k] : 0.f;
    }
    __syncthreads();
#pragma unroll
    for (int q = 0; q < 16; q++) {
        int idx = t + q * 256;
        int k = idx >> 6, ul = idx & 63;
        g_uT_h[(size_t)k * UPAD + u0 + ul] = __half_as_ushort(__float2half_rn(st[ul][k]));
    }
}

// ---------------- fused K1+K2 ----------------
// CTA 0..236   : K1 role  (tile = id%79, split = id/79)  g_lp[s] = norm_adj @ item_sv
// CTA 237..518 : K2 role  (tile = id2%94, split = id2/94) g_rp[s] = adj^T @ user_sv
// dyn smem 30720 (max of both roles)
__global__ __launch_bounds__(256, 2) void k12_mma(const float* __restrict__ NA,
                                                  const float* __restrict__ Adj) {
    extern __shared__ __align__(16) char sm[];
    const int t = threadIdx.x, lane = t & 31, w = t >> 5;
    const uint32_t sb = smem_u32(sm);
    const int m0 = (w >> 1) * 32, n0 = (w & 1) * 32;
    const uint32_t boff = (uint32_t)(n0 + (lane & 15)) * 80 + ((lane >> 4) << 4);
    const int brow = t >> 2, bc8 = (t & 3) << 3;
    const int g = lane >> 2, tg = lane & 3;
    const int id = blockIdx.x;

    float acc[2][4][4];
#pragma unroll
    for (int a = 0; a < 2; a++)
#pragma unroll
        for (int b = 0; b < 4; b++)
#pragma unroll
            for (int cc = 0; cc < 4; cc++) acc[a][b][cc] = 0.f;

    float2 ar[8]; uint4 b4h;

    if (id < 237) {
        // ---------------- K1 role: M=128u, N=64k, Kchunk=32i ----------------
        const int tile = id % 79, split = id / 79;
        const int u0 = tile * 128, ibase0 = split * 4000;
        const uint32_t aoff = (uint32_t)(m0 + (lane & 15)) * 80 + ((lane >> 4) << 4);

        auto LDGf = [&](int c) {
            const int ib = ibase0 + c * 32;
#pragma unroll
            for (int q = 0; q < 8; q++) {
                int pidx = t + q * 256;
                int aul = pidx >> 4, ic2 = (pidx & 15) << 1;
                int gu = u0 + aul;
                ar[q] = (gu < UD) ? *(const float2*)(NA + (size_t)gu * ID + ib + ic2)
                                  : make_float2(0.f, 0.f);
            }
            b4h = *(const uint4*)(g_iT_h + (size_t)brow * IPAD + ib + bc8);
        };
        auto STSf = [&](int b) {
            char* ab = sm + b * 10240;
#pragma unroll
            for (int q = 0; q < 8; q++) {
                int pidx = t + q * 256;
                int aul = pidx >> 4, ic2 = (pidx & 15) << 1;
                *(uint32_t*)(ab + aul * 80 + ic2 * 2) = packh2(ar[q].x, ar[q].y);
            }
            *(uint4*)(sm + 20480 + b * 5120 + brow * 80 + ((t & 3) << 4)) = b4h;
        };

        LDGf(0);
        STSf(0);
        __syncthreads();

        for (int c = 0; c < 125; c++) {
            const int b = c & 1;
            if (c + 1 < 125) LDGf(c + 1);
            const uint32_t bah = sb + b * 10240;
            const uint32_t bbh = sb + 20480 + b * 5120;
#pragma unroll
            for (int ks = 0; ks < 2; ks++) {
                uint32_t bh[2][4], ah[2][4];
#pragma unroll
                for (int p = 0; p < 2; p++)
                    ldm4(bh[p], bbh + boff + p * 1280 + ks * 32);
#pragma unroll
                for (int mi = 0; mi < 2; mi++)
                    ldm4(ah[mi], bah + aoff + mi * 1280 + ks * 32);
#pragma unroll
                for (int mi = 0; mi < 2; mi++)
#pragma unroll
                    for (int nt = 0; nt < 4; nt++) {
                        int p = nt >> 1, j = nt & 1;
                        mma_f16(acc[mi][nt], ah[mi], bh[p][j], bh[p][j + 2]);
                    }
            }
            if (c + 1 < 125) STSf(b ^ 1);
            __syncthreads();
        }

        float* dst = g_lp[split];
#pragma unroll
        for (int mi = 0; mi < 2; mi++)
#pragma unroll
            for (int nt = 0; nt < 4; nt++) {
                int row = u0 + m0 + mi * 16 + g;
                int col = n0 + nt * 8 + tg * 2;
                if (row < UD)     *(float2*)(dst + (size_t)row * 64 + col)       = make_float2(acc[mi][nt][0], acc[mi][nt][1]);
                if (row + 8 < UD) *(float2*)(dst + (size_t)(row + 8) * 64 + col) = make_float2(acc[mi][nt][2], acc[mi][nt][3]);
            }
    } else {
        // ---------------- K2 role: M=128i, N=64k, Kchunk=32u ----------------
        const int id2 = id - 237;
        const int tile = id2 % 94, split = id2 / 94;
        const int i0 = tile * 128, ubase0 = split * 3360;
        const uint32_t aofft = (uint32_t)((lane & 7) + ((lane >> 4) << 3)) * 272
                             + (uint32_t)(m0 + (((lane >> 3) & 1) << 3)) * 2;

        auto LDGf = [&](int c) {
            const int ub = ubase0 + c * 32;
#pragma unroll
            for (int q = 0; q < 8; q++) {
                int pidx = t + q * 256;
                int aul = pidx >> 6, i2 = (pidx & 63) << 1;
                int gu = ub + aul;
                ar[q] = (gu < UD) ? *(const float2*)(Adj + (size_t)gu * ID + i0 + i2)
                                  : make_float2(0.f, 0.f);
            }
            b4h = *(const uint4*)(g_uT_h + (size_t)brow * UPAD + ub + bc8);
        };
        auto STSf = [&](int b) {
            char* ab = sm + b * 8704;
#pragma unroll
            for (int q = 0; q < 8; q++) {
                int pidx = t + q * 256;
                int aul = pidx >> 6, i2 = (pidx & 63) << 1;
                *(uint32_t*)(ab + aul * 272 + i2 * 2) = packh2(ar[q].x, ar[q].y);
            }
            *(uint4*)(sm + 17408 + b * 5120 + brow * 80 + ((t & 3) << 4)) = b4h;
        };

        LDGf(0);
        STSf(0);
        __syncthreads();

        for (int c = 0; c < 105; c++) {
            const int b = c & 1;
            if (c + 1 < 105) LDGf(c + 1);
            const uint32_t bah = sb + b * 8704;
            const uint32_t bbh = sb + 17408 + b * 5120;
#pragma unroll
            for (int ks = 0; ks < 2; ks++) {
                uint32_t bh[2][4], ah[2][4];
#pragma unroll
                for (int p = 0; p < 2; p++)
                    ldm4(bh[p], bbh + boff + p * 1280 + ks * 32);
#pragma unroll
                for (int mi = 0; mi < 2; mi++)
                    ldm4t(ah[mi], bah + aofft + mi * 32 + ks * 4352);
#pragma unroll
                for (int mi = 0; mi < 2; mi++)
#pragma unroll
                    for (int nt = 0; nt < 4; nt++) {
                        int p = nt >> 1, j = nt & 1;
                        mma_f16(acc[mi][nt], ah[mi], bh[p][j], bh[p][j + 2]);
                    }
            }
            if (c + 1 < 105) STSf(b ^ 1);
            __syncthreads();
        }

        float* dst = g_rp[split];
#pragma unroll
        for (int mi = 0; mi < 2; mi++)
#pragma unroll
            for (int nt = 0; nt < 4; nt++) {
                int row = i0 + m0 + mi * 16 + g;
                int col = n0 + nt * 8 + tg * 2;
                if (row < ID)     *(float2*)(dst + (size_t)row * 64 + col)       = make_float2(acc[mi][nt][0], acc[mi][nt][1]);
                if (row + 8 < ID) *(float2*)(dst + (size_t)(row + 8) * 64 + col) = make_float2(acc[mi][nt][2], acc[mi][nt][3]);
            }
    }
}

// ---------------- fused reductions + fp16 pack ----------------
__global__ __launch_bounds__(256) void red_lr(const float* __restrict__ lam) {
    int idx = blockIdx.x * 256 + threadIdx.x;
    if (idx < UPAD * 64) {
        int u = idx >> 6;
        float v = 0.f;
        if (u < UD) v = (g_lp[0][idx] + g_lp[1][idx] + g_lp[2][idx]) / lam[idx & 63];
        g_l_h[idx] = __half_as_ushort(__float2half_rn(v));
    } else {
        int idx2 = idx - UPAD * 64;
        if (idx2 >= IPAD * 64) return;
        int i = idx2 >> 6;
        float v = 0.f;
        if (i < ID) v = g_rp[0][idx2] + g_rp[1][idx2] + g_rp[2][idx2];
        g_r_h[idx2] = __half_as_ushort(__float2half_rn(v));
    }
}

// ---------------- K3: out[u][i] = g_l @ g_r^T  (M=128u, N=128i, K=64, single pass) ---------------
// dyn smem 36864: A(g_l) @0, B(g_r) @18432  (pitch 144)
__global__ __launch_bounds__(256, 2) void k3_mma(float* __restrict__ out) {
    extern __shared__ __align__(16) char sm[];
    const int t = threadIdx.x, lane = t & 31, w = t >> 5;
    const uint32_t sb = smem_u32(sm);
    const int u0 = blockIdx.x * 128, i0 = blockIdx.y * 128;
    const int m0 = (w >> 2) * 64, n0 = (w & 3) * 32;
    const uint32_t abase = (uint32_t)(m0 + (lane & 15)) * 144 + ((lane >> 4) << 4);
    const uint32_t bbase = (uint32_t)(n0 + (lane & 15)) * 144 + ((lane >> 4) << 4);

#pragma unroll
    for (int q = 0; q < 4; q++) {
        int idx = t + q * 256;
        int row = idx >> 3, c8 = (idx & 7) << 3;
        *(uint4*)(sm + row * 144 + c8 * 2)         = *(const uint4*)(g_l_h + (size_t)(u0 + row) * 64 + c8);
        *(uint4*)(sm + 18432 + row * 144 + c8 * 2) = *(const uint4*)(g_r_h + (size_t)(i0 + row) * 64 + c8);
    }
    __syncthreads();

    float acc[4][4][4];
#pragma unroll
    for (int a = 0; a < 4; a++)
#pragma unroll
        for (int b = 0; b < 4; b++)
#pragma unroll
            for (int cc = 0; cc < 4; cc++) acc[a][b][cc] = 0.f;

#pragma unroll
    for (int ks = 0; ks < 4; ks++) {
        uint32_t bh[2][4];
#pragma unroll
        for (int p = 0; p < 2; p++)
            ldm4(bh[p], sb + 18432 + bbase + p * 2304 + ks * 32);
#pragma unroll
        for (int mi = 0; mi < 4; mi++) {
            uint32_t ah[4];
            ldm4(ah, sb + abase + mi * 2304 + ks * 32);
#pragma unroll
            for (int nt = 0; nt < 4; nt++) {
                int p = nt >> 1, j = nt & 1;
                mma_f16(acc[mi][nt], ah, bh[p][j], bh[p][j + 2]);
            }
        }
    }

    const int g = lane >> 2, tg = lane & 3;
#pragma unroll
    for (int mi = 0; mi < 4; mi++)
#pragma unroll
        for (int nt = 0; nt < 4; nt++) {
            int row = u0 + m0 + mi * 16 + g;
            int col = i0 + n0 + nt * 8 + tg * 2;
            if (col < ID) {
                if (row < UD)
                    __stcs((float2*)(out + (size_t)row * ID + col),
                           make_float2(acc[mi][nt][0], acc[mi][nt][1]));
                if (row + 8 < UD)
                    __stcs((float2*)(out + (size_t)(row + 8) * ID + col),
                           make_float2(acc[mi][nt][2], acc[mi][nt][3]));
            }
        }
}

// ---------------- launch ----------------
extern "C" void kernel_launch(void* const* d_in, const int* in_sizes, int n_in,
                              void* d_out, int out_size) {
    const float* lambda_mat = (const float*)d_in[0];
    const float* user_sv    = (const float*)d_in[1];
    const float* item_sv    = (const float*)d_in[2];
    const float* adj_mat    = (const float*)d_in[3];
    const float* norm_adj   = (const float*)d_in[4];
    float* out = (float*)d_out;

    cudaFuncSetAttribute(k12_mma, cudaFuncAttributeMaxDynamicSharedMemorySize, 30720);
    cudaFuncSetAttribute(k3_mma, cudaFuncAttributeMaxDynamicSharedMemorySize, 36864);

    p_item<<<IPAD / 64, 256>>>(item_sv);
    p_user<<<UPAD / 64, 256>>>(user_sv);
    k12_mma<<<237 + 282, 256, 30720>>>(norm_adj, adj_mat);
    red_lr<<<((UPAD + IPAD) * 64 + 255) / 256, 256>>>(lambda_mat);
    k3_mma<<<dim3(79, 94), 256, 36864>>>(out);
}

// round 13
// speedup vs baseline: 1.5903x; 1.0255x over previous
#include <cuda_runtime.h>
#include <cuda_fp16.h>
#include <cstdint>

#define UD 10000
#define ID 12000
#define IPAD 12032   // g_r pitch rows (94*128)
#define UPAD 10112   // g_l pitch rows (79*128)
#define IPAD2 12288  // item^T table pitch: 3*4096
#define UPAD2 10368  // user^T table pitch: 3*3456

// ---------------- scratch ----------------
__device__ __align__(16) uint16_t g_iT_h[64 * IPAD2];                // item_sv^T fp16 [k][i]
__device__ __align__(16) uint16_t g_uT_h[64 * UPAD2];                // user_sv^T fp16 [k][u]
__device__ __align__(16) float    g_lp[3][(size_t)UD * 64];          // K1 partials [u][k]
__device__ __align__(16) float    g_rp[3][(size_t)ID * 64];          // K2 partials [i][k]
__device__ __align__(16) uint16_t g_l_h[UPAD * 64];                  // left*invL fp16 [u][k]
__device__ __align__(16) uint16_t g_r_h[IPAD * 64];                  // right^T fp16 [i][k]

// ---------------- helpers ----------------
__device__ __forceinline__ uint32_t smem_u32(const void* p) {
    uint32_t a;
    asm("{ .reg .u64 t; cvta.to.shared.u64 t, %1; cvt.u32.u64 %0, t; }" : "=r"(a) : "l"(p));
    return a;
}
__device__ __forceinline__ uint32_t packh2(float x0, float x1) {
    uint32_t r;
    asm("cvt.rn.f16x2.f32 %0, %1, %2;" : "=r"(r) : "f"(x1), "f"(x0));
    return r;
}
__device__ __forceinline__ void ldm4(uint32_t* r, uint32_t a) {
    asm volatile("ldmatrix.sync.aligned.m8n8.x4.shared.b16 {%0,%1,%2,%3},[%4];"
                 : "=r"(r[0]), "=r"(r[1]), "=r"(r[2]), "=r"(r[3]) : "r"(a));
}
__device__ __forceinline__ void ldm4t(uint32_t* r, uint32_t a) {
    asm volatile("ldmatrix.sync.aligned.m8n8.x4.trans.shared.b16 {%0,%1,%2,%3},[%4];"
                 : "=r"(r[0]), "=r"(r[1]), "=r"(r[2]), "=r"(r[3]) : "r"(a));
}
__device__ __forceinline__ void mma_f16(float* d, const uint32_t* a, uint32_t b0, uint32_t b1) {
    asm volatile("mma.sync.aligned.m16n8k16.row.col.f32.f16.f16.f32 "
                 "{%0,%1,%2,%3},{%4,%5,%6,%7},{%8,%9},{%0,%1,%2,%3};"
                 : "+f"(d[0]), "+f"(d[1]), "+f"(d[2]), "+f"(d[3])
                 : "r"(a[0]), "r"(a[1]), "r"(a[2]), "r"(a[3]), "r"(b0), "r"(b1));
}

// ---------------- prep: tiled transpose + fp16 ----------------
__global__ __launch_bounds__(256) void p_item(const float* __restrict__ isv) {
    __shared__ float st[64][65];
    const int t = threadIdx.x, i0 = blockIdx.x * 64;
#pragma unroll
    for (int q = 0; q < 16; q++) {
        int idx = t + q * 256;
        int il = idx >> 6, k = idx & 63, gi = i0 + il;
        st[il][k] = (gi < ID) ? isv[(size_t)gi * 64 + k] : 0.f;
    }
    __syncthreads();
#pragma unroll
    for (int q = 0; q < 16; q++) {
        int idx = t + q * 256;
        int k = idx >> 6, il = idx & 63;
        g_iT_h[(size_t)k * IPAD2 + i0 + il] = __half_as_ushort(__float2half_rn(st[il][k]));
    }
}
__global__ __launch_bounds__(256) void p_user(const float* __restrict__ usv) {
    __shared__ float st[64][65];
    const int t = threadIdx.x, u0 = blockIdx.x * 64;
#pragma unroll
    for (int q = 0; q < 16; q++) {
        int idx = t + q * 256;
        int ul = idx >> 6, k = idx & 63, gu = u0 + ul;
        st[ul][k] = (gu < UD) ? usv[(size_t)gu * 64 + k] : 0.f;
    }
    __syncthreads();
#pragma unroll
    for (int q = 0; q < 16; q++) {
        int idx = t + q * 256;
        int k = idx >> 6, ul = idx & 63;
        g_uT_h[(size_t)k * UPAD2 + u0 + ul] = __half_as_ushort(__float2half_rn(st[ul][k]));
    }
}

// ---------------- fused K1+K2, K-chunk 64, 2-buf, half-batch interleave ----------------
// CTA 0..236   : K1  (tile=id%79, split=id/79)   g_lp[s] = norm_adj @ item_sv   64 chunks of 64 i
// CTA 237..518 : K2  (tile=id2%94, split=id2/94) g_rp[s] = adj^T @ user_sv      54 chunks of 64 u
// K1 smem: A[b]@b*18432 (128 rows x 144), B[b]@36864+b*9216 (64 rows x 144)   -> 55296
// K2 smem: A[b]@b*17408 (64 rows x 272),  B[b]@34816+b*9216 (64 rows x 144)   -> 53248
__global__ __launch_bounds__(256, 2) void k12_mma(const float* __restrict__ NA,
                                                  const float* __restrict__ Adj) {
    extern __shared__ __align__(16) char sm[];
    const int t = threadIdx.x, lane = t & 31, w = t >> 5;
    const uint32_t sb = smem_u32(sm);
    const int m0 = (w >> 1) * 32, n0 = (w & 1) * 32;
    const uint32_t boff = (uint32_t)(n0 + (lane & 15)) * 144 + ((lane >> 4) << 4);
    const int g = lane >> 2, tg = lane & 3;
    const int id = blockIdx.x;

    float acc[2][4][4];
#pragma unroll
    for (int a = 0; a < 2; a++)
#pragma unroll
        for (int b = 0; b < 4; b++)
#pragma unroll
            for (int cc = 0; cc < 4; cc++) acc[a][b][cc] = 0.f;

    float2 ar[8]; uint4 b4;

    if (id < 237) {
        // ---------------- K1 role: M=128u, N=64k, Kchunk=64i ----------------
        const int tile = id % 79, split = id / 79;
        const int u0 = tile * 128, ibase0 = split * 4096;
        const uint32_t aoff = (uint32_t)(m0 + (lane & 15)) * 144 + ((lane >> 4) << 4);

        auto LDGf = [&](int c, int h) {
            const int ib = ibase0 + c * 64;
            const int ic2 = ((t & 15) << 1) + h * 32;
            const int gi = ib + ic2;
            const bool gok = gi < ID;
#pragma unroll
            for (int q = 0; q < 8; q++) {
                int gu = u0 + (t >> 4) + q * 16;
                ar[q] = (gok && gu < UD) ? *(const float2*)(NA + (size_t)gu * ID + gi)
                                         : make_float2(0.f, 0.f);
            }
            b4 = *(const uint4*)(g_iT_h + (size_t)(t >> 2) * IPAD2 + ib + ((t & 3) << 3) + h * 32);
        };
        auto STSf = [&](int b, int h) {
            char* ab = sm + b * 18432;
            const int ic2 = ((t & 15) << 1) + h * 32;
#pragma unroll
            for (int q = 0; q < 8; q++) {
                int row = (t >> 4) + q * 16;
                *(uint32_t*)(ab + row * 144 + ic2 * 2) = packh2(ar[q].x, ar[q].y);
            }
            *(uint4*)(sm + 36864 + b * 9216 + (t >> 2) * 144 + ((t & 3) << 4) + h * 64) = b4;
        };

        LDGf(0, 0); STSf(0, 0); LDGf(0, 1); STSf(0, 1);
        __syncthreads();

        for (int c = 0; c < 64; c++) {
            const int b = c & 1;
            const bool more = (c + 1 < 64);
            if (more) LDGf(c + 1, 0);
            const uint32_t bah = sb + b * 18432;
            const uint32_t bbh = sb + 36864 + b * 9216;
#pragma unroll
            for (int ks = 0; ks < 2; ks++) {
                uint32_t bh[2][4], ah[2][4];
#pragma unroll
                for (int p = 0; p < 2; p++)
                    ldm4(bh[p], bbh + boff + p * 2304 + ks * 32);
#pragma unroll
                for (int mi = 0; mi < 2; mi++)
                    ldm4(ah[mi], bah + aoff + mi * 2304 + ks * 32);
#pragma unroll
                for (int mi = 0; mi < 2; mi++)
#pragma unroll
                    for (int nt = 0; nt < 4; nt++) {
                        int p = nt >> 1, j = nt & 1;
                        mma_f16(acc[mi][nt], ah[mi], bh[p][j], bh[p][j + 2]);
                    }
            }
            if (more) { STSf(b ^ 1, 0); LDGf(c + 1, 1); }
#pragma unroll
            for (int ks = 2; ks < 4; ks++) {
                uint32_t bh[2][4], ah[2][4];
#pragma unroll
                for (int p = 0; p < 2; p++)
                    ldm4(bh[p], bbh + boff + p * 2304 + ks * 32);
#pragma unroll
                for (int mi = 0; mi < 2; mi++)
                    ldm4(ah[mi], bah + aoff + mi * 2304 + ks * 32);
#pragma unroll
                for (int mi = 0; mi < 2; mi++)
#pragma unroll
                    for (int nt = 0; nt < 4; nt++) {
                        int p = nt >> 1, j = nt & 1;
                        mma_f16(acc[mi][nt], ah[mi], bh[p][j], bh[p][j + 2]);
                    }
            }
            if (more) STSf(b ^ 1, 1);
            __syncthreads();
        }

        float* dst = g_lp[split];
#pragma unroll
        for (int mi = 0; mi < 2; mi++)
#pragma unroll
            for (int nt = 0; nt < 4; nt++) {
                int row = u0 + m0 + mi * 16 + g;
                int col = n0 + nt * 8 + tg * 2;
                if (row < UD)     *(float2*)(dst + (size_t)row * 64 + col)       = make_float2(acc[mi][nt][0], acc[mi][nt][1]);
                if (row + 8 < UD) *(float2*)(dst + (size_t)(row + 8) * 64 + col) = make_float2(acc[mi][nt][2], acc[mi][nt][3]);
            }
    } else {
        // ---------------- K2 role: M=128i, N=64k, Kchunk=64u ----------------
        const int id2 = id - 237;
        const int tile = id2 % 94, split = id2 / 94;
        const int i0 = tile * 128, ubase0 = split * 3456;
        const uint32_t aofft = (uint32_t)((lane & 7) + ((lane >> 4) << 3)) * 272
                             + (uint32_t)(m0 + (((lane >> 3) & 1) << 3)) * 2;

        auto LDGf = [&](int c, int h) {
            const int ub = ubase0 + c * 64;
            const int i2 = (t & 63) << 1;
            const bool iok = (i0 + i2) < ID;
#pragma unroll
            for (int q = 0; q < 8; q++) {
                int gu = ub + (t >> 6) + q * 4 + h * 32;
                ar[q] = (iok && gu < UD) ? *(const float2*)(Adj + (size_t)gu * ID + i0 + i2)
                                         : make_float2(0.f, 0.f);
            }
            b4 = *(const uint4*)(g_uT_h + (size_t)(t >> 2) * UPAD2 + ub + ((t & 3) << 3) + h * 32);
        };
        auto STSf = [&](int b, int h) {
            char* ab = sm + b * 17408;
            const int i2 = (t & 63) << 1;
#pragma unroll
            for (int q = 0; q < 8; q++) {
                int aul = (t >> 6) + q * 4 + h * 32;
                *(uint32_t*)(ab + aul * 272 + i2 * 2) = packh2(ar[q].x, ar[q].y);
            }
            *(uint4*)(sm + 34816 + b * 9216 + (t >> 2) * 144 + ((t & 3) << 4) + h * 64) = b4;
        };

        LDGf(0, 0); STSf(0, 0); LDGf(0, 1); STSf(0, 1);
        __syncthreads();

        for (int c = 0; c < 54; c++) {
            const int b = c & 1;
            const bool more = (c + 1 < 54);
            if (more) LDGf(c + 1, 0);
            const uint32_t bah = sb + b * 17408;
            const uint32_t bbh = sb + 34816 + b * 9216;
#pragma unroll
            for (int ks = 0; ks < 2; ks++) {
                uint32_t bh[2][4], ah[2][4];
#pragma unroll
                for (int p = 0; p < 2; p++)
                    ldm4(bh[p], bbh + boff + p * 2304 + ks * 32);
#pragma unroll
                for (int mi = 0; mi < 2; mi++)
                    ldm4t(ah[mi], bah + aofft + mi * 32 + ks * 4352);
#pragma unroll
                for (int mi = 0; mi < 2; mi++)
#pragma unroll
                    for (int nt = 0; nt < 4; nt++) {
                        int p = nt >> 1, j = nt & 1;
                        mma_f16(acc[mi][nt], ah[mi], bh[p][j], bh[p][j + 2]);
                    }
            }
            if (more) { STSf(b ^ 1, 0); LDGf(c + 1, 1); }
#pragma unroll
            for (int ks = 2; ks < 4; ks++) {
                uint32_t bh[2][4], ah[2][4];
#pragma unroll
                for (int p = 0; p < 2; p++)
                    ldm4(bh[p], bbh + boff + p * 2304 + ks * 32);
#pragma unroll
                for (int mi = 0; mi < 2; mi++)
                    ldm4t(ah[mi], bah + aofft + mi * 32 + ks * 4352);
#pragma unroll
                for (int mi = 0; mi < 2; mi++)
#pragma unroll
                    for (int nt = 0; nt < 4; nt++) {
                        int p = nt >> 1, j = nt & 1;
                        mma_f16(acc[mi][nt], ah[mi], bh[p][j], bh[p][j + 2]);
                    }
            }
            if (more) STSf(b ^ 1, 1);
            __syncthreads();
        }

        float* dst = g_rp[split];
#pragma unroll
        for (int mi = 0; mi < 2; mi++)
#pragma unroll
            for (int nt = 0; nt < 4; nt++) {
                int row = i0 + m0 + mi * 16 + g;
                int col = n0 + nt * 8 + tg * 2;
                if (row < ID)     *(float2*)(dst + (size_t)row * 64 + col)       = make_float2(acc[mi][nt][0], acc[mi][nt][1]);
                if (row + 8 < ID) *(float2*)(dst + (size_t)(row + 8) * 64 + col) = make_float2(acc[mi][nt][2], acc[mi][nt][3]);
            }
    }
}

// ---------------- fused reductions + fp16 pack ----------------
__global__ __launch_bounds__(256) void red_lr(const float* __restrict__ lam) {
    int idx = blockIdx.x * 256 + threadIdx.x;
    if (idx < UPAD * 64) {
        int u = idx >> 6;
        float v = 0.f;
        if (u < UD) v = (g_lp[0][idx] + g_lp[1][idx] + g_lp[2][idx]) / lam[idx & 63];
        g_l_h[idx] = __half_as_ushort(__float2half_rn(v));
    } else {
        int idx2 = idx - UPAD * 64;
        if (idx2 >= IPAD * 64) return;
        int i = idx2 >> 6;
        float v = 0.f;
        if (i < ID) v = g_rp[0][idx2] + g_rp[1][idx2] + g_rp[2][idx2];
        g_r_h[idx2] = __half_as_ushort(__float2half_rn(v));
    }
}

// ---------------- K3: out[u][i] = g_l @ g_r^T  (M=128u, N=128i, K=64, single pass) ---------------
__global__ __launch_bounds__(256, 2) void k3_mma(float* __restrict__ out) {
    extern __shared__ __align__(16) char sm[];
    const int t = threadIdx.x, lane = t & 31, w = t >> 5;
    const uint32_t sb = smem_u32(sm);
    const int u0 = blockIdx.x * 128, i0 = blockIdx.y * 128;
    const int m0 = (w >> 2) * 64, n0 = (w & 3) * 32;
    const uint32_t abase = (uint32_t)(m0 + (lane & 15)) * 144 + ((lane >> 4) << 4);
    const uint32_t bbase = (uint32_t)(n0 + (lane & 15)) * 144 + ((lane >> 4) << 4);

#pragma unroll
    for (int q = 0; q < 4; q++) {
        int idx = t + q * 256;
        int row = idx >> 3, c8 = (idx & 7) << 3;
        *(uint4*)(sm + row * 144 + c8 * 2)         = *(const uint4*)(g_l_h + (size_t)(u0 + row) * 64 + c8);
        *(uint4*)(sm + 18432 + row * 144 + c8 * 2) = *(const uint4*)(g_r_h + (size_t)(i0 + row) * 64 + c8);
    }
    __syncthreads();

    float acc[4][4][4];
#pragma unroll
    for (int a = 0; a < 4; a++)
#pragma unroll
        for (int b = 0; b < 4; b++)
#pragma unroll
            for (int cc = 0; cc < 4; cc++) acc[a][b][cc] = 0.f;

#pragma unroll
    for (int ks = 0; ks < 4; ks++) {
        uint32_t bh[2][4];
#pragma unroll
        for (int p = 0; p < 2; p++)
            ldm4(bh[p], sb + 18432 + bbase + p * 2304 + ks * 32);
#pragma unroll
        for (int mi = 0; mi < 4; mi++) {
            uint32_t ah[4];
            ldm4(ah, sb + abase + mi * 2304 + ks * 32);
#pragma unroll
            for (int nt = 0; nt < 4; nt++) {
                int p = nt >> 1, j = nt & 1;
                mma_f16(acc[mi][nt], ah, bh[p][j], bh[p][j + 2]);
            }
        }
    }

    const int g = lane >> 2, tg = lane & 3;
#pragma unroll
    for (int mi = 0; mi < 4; mi++)
#pragma unroll
        for (int nt = 0; nt < 4; nt++) {
            int row = u0 + m0 + mi * 16 + g;
            int col = i0 + n0 + nt * 8 + tg * 2;
            if (col < ID) {
                if (row < UD)
                    __stcs((float2*)(out + (size_t)row * ID + col),
                           make_float2(acc[mi][nt][0], acc[mi][nt][1]));
                if (row + 8 < UD)
                    __stcs((float2*)(out + (size_t)(row + 8) * ID + col),
                           make_float2(acc[mi][nt][2], acc[mi][nt][3]));
            }
        }
}

// ---------------- launch ----------------
extern "C" void kernel_launch(void* const* d_in, const int* in_sizes, int n_in,
                              void* d_out, int out_size) {
    const float* lambda_mat = (const float*)d_in[0];
    const float* user_sv    = (const float*)d_in[1];
    const float* item_sv    = (const float*)d_in[2];
    const float* adj_mat    = (const float*)d_in[3];
    const float* norm_adj   = (const float*)d_in[4];
    float* out = (float*)d_out;

    cudaFuncSetAttribute(k12_mma, cudaFuncAttributeMaxDynamicSharedMemorySize, 55296);
    cudaFuncSetAttribute(k3_mma, cudaFuncAttributeMaxDynamicSharedMemorySize, 36864);

    p_item<<<IPAD2 / 64, 256>>>(item_sv);
    p_user<<<UPAD2 / 64, 256>>>(user_sv);
    k12_mma<<<237 + 282, 256, 55296>>>(norm_adj, adj_mat);
    red_lr<<<((UPAD + IPAD) * 64 + 255) / 256, 256>>>(lambda_mat);
    k3_mma<<<dim3(79, 94), 256, 36864>>>(out);
}